// round 11
// baseline (speedup 1.0000x reference)
#include <cuda_runtime.h>
#include <cuda_fp16.h>
#include <cstdint>

#define CB    2
#define CHW   4096
#define CHID  1280
#define CCAD  2048
#define CLTXT 77
#define CNT   4
#define CNH   20
#define CENCL (CLTXT + CNT)

#define GM 8192
#define GK 1280
#define GN 1280
#define CBSZ (CB * 80 * CHID)

// ---------------- scratch (device globals) ----------------
__device__ float g_q[(size_t)GM * GK];
__device__ float g_kv[(size_t)4 * CBSZ];
__device__ __half g_hid[(size_t)GM * GK];
__device__ __half g_wq[(size_t)GK * GN];
__device__ __half g_wo[(size_t)GK * GN];
__device__ __half g_attn[(size_t)GM * GK];
__device__ __half g_enc[(size_t)CB * CENCL * CCAD];
__device__ __half g_wk [(size_t)CCAD * CHID];
__device__ __half g_wv [(size_t)CCAD * CHID];
__device__ __half g_wkn[(size_t)CCAD * CHID];
__device__ __half g_wvn[(size_t)CCAD * CHID];

// =====================================================================
// fp32 -> fp16 converts
// =====================================================================
__global__ __launch_bounds__(512) void cvtf(
    const float* __restrict__ x, __half* __restrict__ y, int n)
{
    for (int i = (blockIdx.x * 512 + threadIdx.x) * 4; i < n; i += gridDim.x * 512 * 4) {
        const float4 v = *(const float4*)(x + i);
        *(__half2*)(y + i)     = __floats2half2_rn(v.x, v.y);
        *(__half2*)(y + i + 2) = __floats2half2_rn(v.z, v.w);
    }
}

struct CvtSeg { const float* src; __half* dst; int len; };
struct CvtArgs { CvtSeg s[7]; };

__global__ __launch_bounds__(512) void cvt_multi(CvtArgs a)
{
    const CvtSeg seg = a.s[blockIdx.y];
    const float* __restrict__ x = seg.src;
    __half* __restrict__ y = seg.dst;
    for (int i = (blockIdx.x * 512 + threadIdx.x) * 4; i < seg.len; i += gridDim.x * 512 * 4) {
        const float4 v = *(const float4*)(x + i);
        *(__half2*)(y + i)     = __floats2half2_rn(v.x, v.y);
        *(__half2*)(y + i + 2) = __floats2half2_rn(v.z, v.w);
    }
}

// =====================================================================
// shared mma helpers
// =====================================================================
#define CP_ASYNC(dst, src) asm volatile("cp.async.cg.shared.global [%0], [%1], 16;" :: "r"(dst), "l"(src))
#define CP_ASYNC_Z(dst, src, ok) asm volatile("cp.async.cg.shared.global [%0], [%1], 16, %2;" :: "r"(dst), "l"(src), "r"((ok) ? 16 : 0))

__device__ __forceinline__ void ldsm4(uint32_t* r, uint32_t a) {
    asm volatile("ldmatrix.sync.aligned.m8n8.x4.shared.b16 {%0,%1,%2,%3}, [%4];"
        : "=r"(r[0]), "=r"(r[1]), "=r"(r[2]), "=r"(r[3]) : "r"(a));
}
__device__ __forceinline__ void ldsm4t(uint32_t* r, uint32_t a) {
    asm volatile("ldmatrix.sync.aligned.m8n8.x4.trans.shared.b16 {%0,%1,%2,%3}, [%4];"
        : "=r"(r[0]), "=r"(r[1]), "=r"(r[2]), "=r"(r[3]) : "r"(a));
}
__device__ __forceinline__ void mma16816(float* c, const uint32_t* a, const uint32_t* b) {
    asm volatile("mma.sync.aligned.m16n8k16.row.col.f32.f16.f16.f32 "
        "{%0,%1,%2,%3}, {%4,%5,%6,%7}, {%8,%9}, {%0,%1,%2,%3};"
        : "+f"(c[0]), "+f"(c[1]), "+f"(c[2]), "+f"(c[3])
        : "r"(a[0]), "r"(a[1]), "r"(a[2]), "r"(a[3]), "r"(b[0]), "r"(b[1]));
}

#define A_PITCH 40
#define ABUF (128 * A_PITCH)
#define NSTAGE 4
// proj (128x128 tile) B buffer
#define PB_PITCH 136
#define PBUF (32 * PB_PITCH)
#define PROJ_SMEM ((NSTAGE * ABUF + NSTAGE * PBUF) * 2)
// gemm (128x256 tile) B buffer
#define GB_PITCH 264
#define GBUF (32 * GB_PITCH)
#define GEMM_SMEM ((NSTAGE * ABUF + NSTAGE * GBUF) * 2)

// =====================================================================
// fp16 mma.sync GEMM v5: CTA 128x256, 512 thr / 16 warps (4x4),
// warp tile 32x64. Same mma count as v4, 2x the issuing warps.
// =====================================================================
__global__ __launch_bounds__(512, 1) void gemm_f16(
    const __half* __restrict__ A, const __half* __restrict__ B,
    const float* __restrict__ bias, float* __restrict__ C)
{
    extern __shared__ __align__(16) char sm[];
    __half* sA = (__half*)sm;             // [NSTAGE][128][A_PITCH]
    __half* sB = sA + NSTAGE * ABUF;      // [NSTAGE][32][GB_PITCH]

    const int tid = threadIdx.x;
    const int m0 = blockIdx.x * 128, n0 = blockIdx.y * 256;
    const int lane = tid & 31, warp = tid >> 5;
    const int wm = warp & 3, wn = warp >> 2;   // 4 x 4 warps, warp tile 32x64

    // staging: A 1 row-chunk/thread (128 rows x 32 k), B 2 chunks (32 rows x 256 cols)
    const int arow = tid >> 2, ak8 = (tid & 3) << 3;
    const int brow = tid >> 5, bn8 = (tid & 31) << 3;
    const __half* gA = A + (size_t)(m0 + arow) * GK + ak8;
    const __half* gB = B + (size_t)brow * GN + n0 + bn8;
    const uint32_t dA = (uint32_t)__cvta_generic_to_shared(sA) + (uint32_t)(arow * A_PITCH + ak8) * 2;
    const uint32_t dB = (uint32_t)__cvta_generic_to_shared(sB) + (uint32_t)(brow * GB_PITCH + bn8) * 2;

#define LOADK(stage, kt) do {                                                   \
        const uint32_t ao_ = (uint32_t)(stage) * (ABUF * 2);                    \
        const uint32_t bo_ = (uint32_t)(stage) * (GBUF * 2);                    \
        const size_t ka_ = (size_t)(kt) * 32;                                   \
        CP_ASYNC(dA + ao_, gA + ka_);                                           \
        CP_ASYNC(dB + bo_,                     gB + ka_ * GN);                  \
        CP_ASYNC(dB + bo_ + 16 * GB_PITCH * 2, gB + (ka_ + 16) * GN);           \
        asm volatile("cp.async.commit_group;");                                 \
    } while (0)

    LOADK(0, 0);
    LOADK(1, 1);
    LOADK(2, 2);

    float acc[2][8][4] = {};

    const uint32_t aOff = (uint32_t)((wm * 32 + (lane & 15)) * A_PITCH + ((lane >> 4) << 3)) * 2;
    const uint32_t aB0 = (uint32_t)__cvta_generic_to_shared(sA) + aOff;
    const uint32_t bOff = (uint32_t)(((lane & 7) + ((lane >> 3) & 1) * 8) * GB_PITCH
                                     + wn * 64 + ((lane >> 4) << 3)) * 2;
    const uint32_t bB0 = (uint32_t)__cvta_generic_to_shared(sB) + bOff;

    const int NKT = GK / 32;   // 40
    for (int kt = 0; kt < NKT; kt++) {
        const int s = kt & (NSTAGE - 1);
        if (kt < NKT - 2)       asm volatile("cp.async.wait_group 2;");
        else if (kt == NKT - 2) asm volatile("cp.async.wait_group 1;");
        else                    asm volatile("cp.async.wait_group 0;");
        __syncthreads();

        const uint32_t ah = aB0 + s * (ABUF * 2);
        const uint32_t bh = bB0 + s * (GBUF * 2);
#pragma unroll
        for (int ks = 0; ks < 2; ks++) {
            const uint32_t ka = ah + ks * 32;                       // +16 halves
            const uint32_t kb = bh + ks * (16 * GB_PITCH * 2);      // +16 k-rows
            uint32_t A0[4], A1[4];
            ldsm4(A0, ka);
            ldsm4(A1, ka + 16 * A_PITCH * 2);
            uint32_t Bf[16];
#pragma unroll
            for (int t = 0; t < 4; t++) ldsm4t(Bf + t * 4, kb + t * 32);
#pragma unroll
            for (int j = 0; j < 8; j++) {
                mma16816(acc[0][j], A0, &Bf[j * 2]);
                mma16816(acc[1][j], A1, &Bf[j * 2]);
            }
        }
        if (kt + 3 < NKT) {
            LOADK((kt + 3) & (NSTAGE - 1), kt + 3);
        }
    }

#pragma unroll
    for (int f = 0; f < 2; f++) {
        const int r0 = m0 + wm * 32 + f * 16 + (lane >> 2);
#pragma unroll
        for (int j = 0; j < 8; j++) {
            const int cc = n0 + wn * 64 + j * 8 + ((lane & 3) << 1);
            float b0 = 0.f, b1 = 0.f;
            if (bias) { b0 = bias[cc]; b1 = bias[cc + 1]; }
            *(float2*)(C + (size_t)r0 * GN + cc) =
                make_float2(acc[f][j][0] + b0, acc[f][j][1] + b1);
            *(float2*)(C + (size_t)(r0 + 8) * GN + cc) =
                make_float2(acc[f][j][2] + b0, acc[f][j][3] + b1);
        }
    }
#undef LOADK
}

// =====================================================================
// fp16 projection GEMM, masked M (K/V/KN/VN -> g_kv fp32), CTA 128x128
// =====================================================================
__global__ __launch_bounds__(512, 1) void proj_f16()
{
    extern __shared__ __align__(16) char sm[];
    __half* sA = (__half*)sm;
    __half* sB = sA + NSTAGE * ABUF;

    const int tid = threadIdx.x;
    const int b = blockIdx.x, n0 = blockIdx.y * 128, type = blockIdx.z;
    const int M = (type < 2) ? CLTXT : CNT;
    const __half* Asrc = g_enc + (size_t)b * CENCL * CCAD + ((type >= 2) ? (size_t)CLTXT * CCAD : 0);
    const __half* Bsrc = (type == 0) ? g_wk : (type == 1) ? g_wv : (type == 2) ? g_wkn : g_wvn;
    float* C = g_kv + (size_t)type * CBSZ + (size_t)b * 80 * CHID;

    const int lane = tid & 31, warp = tid >> 5;
    const int wm = warp >> 2, wn = warp & 3;

    const int arow = tid >> 2, ak8 = (tid & 3) << 3;
    const int brow = tid >> 4, bn8 = (tid & 15) << 3;
    const bool aok = arow < M;
    const __half* gA = Asrc + (size_t)arow * CCAD + ak8;
    const __half* gB = Bsrc + (size_t)brow * CHID + n0 + bn8;
    const uint32_t dA = (uint32_t)__cvta_generic_to_shared(sA) + (uint32_t)(arow * A_PITCH + ak8) * 2;
    const uint32_t dB = (uint32_t)__cvta_generic_to_shared(sB) + (uint32_t)(brow * PB_PITCH + bn8) * 2;

#define LOADKP(stage, kt) do {                                                  \
        const uint32_t ao_ = (uint32_t)(stage) * (ABUF * 2);                    \
        const uint32_t bo_ = (uint32_t)(stage) * (PBUF * 2);                    \
        const size_t kofs_ = (size_t)(kt) * 32;                                 \
        CP_ASYNC_Z(dA + ao_, gA + kofs_, aok);                                  \
        CP_ASYNC(dB + bo_, gB + kofs_ * CHID);                                  \
        asm volatile("cp.async.commit_group;");                                 \
    } while (0)

    LOADKP(0, 0);
    LOADKP(1, 1);
    LOADKP(2, 2);

    float acc[2][4][4] = {};

    const uint32_t aOff = (uint32_t)((wm * 32 + (lane & 15)) * A_PITCH + ((lane >> 4) << 3)) * 2;
    const uint32_t aB0 = (uint32_t)__cvta_generic_to_shared(sA) + aOff;
    const uint32_t bOff = (uint32_t)(((lane & 7) + ((lane >> 3) & 1) * 8) * PB_PITCH
                                     + wn * 32 + ((lane >> 4) << 3)) * 2;
    const uint32_t bB0 = (uint32_t)__cvta_generic_to_shared(sB) + bOff;

    const int NKT = CCAD / 32;   // 64
    for (int kt = 0; kt < NKT; kt++) {
        const int s = kt & (NSTAGE - 1);
        if (kt < NKT - 2)       asm volatile("cp.async.wait_group 2;");
        else if (kt == NKT - 2) asm volatile("cp.async.wait_group 1;");
        else                    asm volatile("cp.async.wait_group 0;");
        __syncthreads();

        const uint32_t ah = aB0 + s * (ABUF * 2);
        const uint32_t bh = bB0 + s * (PBUF * 2);
#pragma unroll
        for (int ks = 0; ks < 2; ks++) {
            const uint32_t ka = ah + ks * 32;
            const uint32_t kb = bh + ks * (16 * PB_PITCH * 2);
            uint32_t A0[4], A1[4];
            ldsm4(A0, ka);
            ldsm4(A1, ka + 16 * A_PITCH * 2);
            uint32_t Bf[8];
            ldsm4t(Bf,     kb);
            ldsm4t(Bf + 4, kb + 32);
#pragma unroll
            for (int j = 0; j < 4; j++) {
                mma16816(acc[0][j], A0, &Bf[j * 2]);
                mma16816(acc[1][j], A1, &Bf[j * 2]);
            }
        }
        if (kt + 3 < NKT) {
            LOADKP((kt + 3) & (NSTAGE - 1), kt + 3);
        }
    }

#pragma unroll
    for (int fm = 0; fm < 2; fm++) {
        const int r0 = wm * 32 + fm * 16 + (lane >> 2);
#pragma unroll
        for (int j = 0; j < 4; j++) {
            const int cc = n0 + wn * 32 + j * 8 + ((lane & 3) << 1);
            if (r0 < M)
                *(float2*)(C + (size_t)r0 * CHID + cc) =
                    make_float2(acc[fm][j][0], acc[fm][j][1]);
            if (r0 + 8 < M)
                *(float2*)(C + (size_t)(r0 + 8) * CHID + cc) =
                    make_float2(acc[fm][j][2], acc[fm][j][3]);
        }
    }
#undef LOADKP
}

// =====================================================================
// Attention: token-batched phase 3; output fp16
// =====================================================================
struct SmA {
    float Qs[2][64][68];
    float Ks[2][CLTXT][68];
    float Vs[2][CLTXT][68];
    float KNs[2][CNT][68];
    float VNs[2][CNT][68];
    float Wbuf[8][8][80];
};

__global__ __launch_bounds__(256, 1) void qattn_lite(const int* __restrict__ idx_alter)
{
    extern __shared__ char raw[];
    SmA& S = *reinterpret_cast<SmA*>(raw);
    const int b  = blockIdx.x >> 6;
    const int t0 = (blockIdx.x & 63) << 6;
    const int h0 = blockIdx.y * 2;
    const int tid = threadIdx.x;

    for (int i = tid; i < 64 * 32; i += 256) {
        const int t = i >> 5, c4 = (i & 31) << 2;
        const int hh = c4 >> 6, d = c4 & 63;
        float4 q = *(const float4*)(g_q + ((size_t)b * CHW + t0 + t) * CHID + h0 * 64 + c4);
        q.x *= 0.125f; q.y *= 0.125f; q.z *= 0.125f; q.w *= 0.125f;
        *(float4*)&S.Qs[hh][t][d] = q;
    }

#pragma unroll
    for (int hh = 0; hh < 2; hh++) {
        const size_t cb = (size_t)(h0 + hh) * 64;
        const float* kK = g_kv + (size_t)0 * CBSZ + (size_t)b * 80 * CHID + cb;
        const float* kV = g_kv + (size_t)1 * CBSZ + (size_t)b * 80 * CHID + cb;
        for (int i = tid; i < CLTXT * 16; i += 256) {
            const int j = i >> 4, d4 = (i & 15) << 2;
            *(float4*)&S.Ks[hh][j][d4] = *(const float4*)(kK + (size_t)j * CHID + d4);
            *(float4*)&S.Vs[hh][j][d4] = *(const float4*)(kV + (size_t)j * CHID + d4);
        }
        const float* kKN = g_kv + (size_t)2 * CBSZ + (size_t)b * 80 * CHID + cb;
        const float* kVN = g_kv + (size_t)3 * CBSZ + (size_t)b * 80 * CHID + cb;
        for (int i = tid; i < CNT * 16; i += 256) {
            const int j = i >> 4, d4 = (i & 15) << 2;
            *(float4*)&S.KNs[hh][j][d4] = *(const float4*)(kKN + (size_t)j * CHID + d4);
            *(float4*)&S.VNs[hh][j][d4] = *(const float4*)(kVN + (size_t)j * CHID + d4);
        }
    }
    const int sidx = idx_alter[b];
    __syncthreads();

    const int warp = tid >> 5, lane = tid & 31;
    const int j0 = lane, j1 = lane + 32, j2 = lane + 64;
    const bool j2ok = (j2 < CLTXT);
    const int j2c = j2ok ? j2 : 0;
    const int d0 = lane << 1;

#pragma unroll
    for (int hh = 0; hh < 2; hh++) {
        const float* k0p = S.Ks[hh][j0];
        const float* k1p = S.Ks[hh][j1];
        const float* k2p = S.Ks[hh][j2c];
        const float* knp = S.KNs[hh][lane & 3];

        float l0[8], l1[8], l2[8], ln[8];
#pragma unroll
        for (int it = 0; it < 8; it++) { l0[it] = l1[it] = l2[it] = ln[it] = 0.f; }

#pragma unroll 4
        for (int d4 = 0; d4 < 64; d4 += 4) {
            const float4 x  = *(const float4*)(k0p + d4);
            const float4 y  = *(const float4*)(k1p + d4);
            const float4 z  = *(const float4*)(k2p + d4);
            const float4 w4 = *(const float4*)(knp + d4);
#pragma unroll
            for (int it = 0; it < 8; it++) {
                const float4 q = *(const float4*)(&S.Qs[hh][warp * 8 + it][d4]);
                l0[it] += q.x * x.x + q.y * x.y + q.z * x.z + q.w * x.w;
                l1[it] += q.x * y.x + q.y * y.y + q.z * y.z + q.w * y.w;
                l2[it] += q.x * z.x + q.y * z.y + q.z * z.z + q.w * z.w;
                ln[it] += q.x * w4.x + q.y * w4.y + q.z * w4.z + q.w * w4.w;
            }
        }

        const float2 vsel = *(const float2*)&S.Vs[hh][sidx][d0];
        const float2 a0v = *(const float2*)&S.VNs[hh][0][d0];
        const float2 a1v = *(const float2*)&S.VNs[hh][1][d0];
        const float2 a2v = *(const float2*)&S.VNs[hh][2][d0];
        const float2 a3v = *(const float2*)&S.VNs[hh][3][d0];
        float vix[8], viy[8];
#pragma unroll
        for (int it = 0; it < 8; it++) {
            const float a0 = l0[it], a1 = l1[it];
            const float a2 = j2ok ? l2[it] : -1e30f;
            float lm = fmaxf(fmaxf(a0, a1), a2);
#pragma unroll
            for (int o = 16; o; o >>= 1) lm = fmaxf(lm, __shfl_xor_sync(0xffffffffu, lm, o));
            const float e0 = __expf(a0 - lm);
            const float e1 = __expf(a1 - lm);
            const float e2 = j2ok ? __expf(a2 - lm) : 0.f;
            float es = e0 + e1 + e2;
#pragma unroll
            for (int o = 16; o; o >>= 1) es += __shfl_xor_sync(0xffffffffu, es, o);
            const float inv = 1.f / es;
            float* wrow = S.Wbuf[warp][it];
            wrow[j0] = e0 * inv;
            wrow[j1] = e1 * inv;
            if (j2ok) wrow[j2] = e2 * inv;

            float lnv = (lane < CNT) ? ln[it] : -1e30f;
            float mn = lnv;
            mn = fmaxf(mn, __shfl_xor_sync(0xffffffffu, mn, 1));
            mn = fmaxf(mn, __shfl_xor_sync(0xffffffffu, mn, 2));
            const float en = __expf(lnv - mn);
            float sn = en;
            sn += __shfl_xor_sync(0xffffffffu, sn, 1);
            sn += __shfl_xor_sync(0xffffffffu, sn, 2);
            const float wnv = en / sn;
            const float wn0 = __shfl_sync(0xffffffffu, wnv, 0);
            const float wn1 = __shfl_sync(0xffffffffu, wnv, 1);
            const float wn2 = __shfl_sync(0xffffffffu, wnv, 2);
            const float wn3 = __shfl_sync(0xffffffffu, wnv, 3);
            vix[it] = wn0 * a0v.x + wn1 * a1v.x + wn2 * a2v.x + wn3 * a3v.x;
            viy[it] = wn0 * a0v.y + wn1 * a1v.y + wn2 * a2v.y + wn3 * a3v.y;
        }
        __syncwarp();

        float bx[8], by[8];
#pragma unroll
        for (int it = 0; it < 8; it++) { bx[it] = 0.f; by[it] = 0.f; }
#pragma unroll 7
        for (int j = 0; j < CLTXT; j++) {
            const float2 vv = *(const float2*)&S.Vs[hh][j][d0];
#pragma unroll
            for (int it = 0; it < 8; it++) {
                const float wj = S.Wbuf[warp][it][j];
                bx[it] += wj * vv.x;
                by[it] += wj * vv.y;
            }
        }

#pragma unroll
        for (int it = 0; it < 8; it++) {
            const float wsel = S.Wbuf[warp][it][sidx];
            const float ox = bx[it] + wsel * (vix[it] - vsel.x);
            const float oy = by[it] + wsel * (viy[it] - vsel.y);
            const int t = warp * 8 + it;
            const size_t off = ((size_t)b * CHW + t0 + t) * CHID + (h0 + hh) * 64 + d0;
            *(__half2*)(g_attn + off) = __floats2half2_rn(ox, oy);
        }
        __syncwarp();
    }
}

// ---------------- launch ----------------
extern "C" void kernel_launch(void* const* d_in, const int* in_sizes, int n_in,
                              void* d_out, int out_size)
{
    (void)in_sizes; (void)n_in; (void)out_size;
    const float* hidden = (const float*)d_in[0];
    const float* enc    = (const float*)d_in[1];
    const int*   idx    = (const int*)  d_in[2];
    const float* Wq     = (const float*)d_in[3];
    const float* Wk     = (const float*)d_in[4];
    const float* Wv     = (const float*)d_in[5];
    const float* Wkn    = (const float*)d_in[6];
    const float* Wvn    = (const float*)d_in[7];
    const float* Wout   = (const float*)d_in[8];
    const float* bout   = (const float*)d_in[9];
    float* out = (float*)d_out;

    __half *hidp, *wqp, *wop, *atp, *encp, *wkp, *wvp, *wknp, *wvnp;
    float* qp;
    cudaGetSymbolAddress((void**)&hidp, g_hid);
    cudaGetSymbolAddress((void**)&wqp,  g_wq);
    cudaGetSymbolAddress((void**)&wop,  g_wo);
    cudaGetSymbolAddress((void**)&atp,  g_attn);
    cudaGetSymbolAddress((void**)&encp, g_enc);
    cudaGetSymbolAddress((void**)&wkp,  g_wk);
    cudaGetSymbolAddress((void**)&wvp,  g_wv);
    cudaGetSymbolAddress((void**)&wknp, g_wkn);
    cudaGetSymbolAddress((void**)&wvnp, g_wvn);
    cudaGetSymbolAddress((void**)&qp,   g_q);

    cudaFuncSetAttribute(gemm_f16, cudaFuncAttributeMaxDynamicSharedMemorySize, GEMM_SMEM);
    cudaFuncSetAttribute(proj_f16, cudaFuncAttributeMaxDynamicSharedMemorySize, PROJ_SMEM);
    cudaFuncSetAttribute(qattn_lite, cudaFuncAttributeMaxDynamicSharedMemorySize, (int)sizeof(SmA));

    // 1) batched weight/enc conversions
    CvtArgs ca;
    ca.s[0] = { Wq,   wqp,  GK * GN };
    ca.s[1] = { Wout, wop,  GK * GN };
    ca.s[2] = { Wk,   wkp,  CCAD * CHID };
    ca.s[3] = { Wv,   wvp,  CCAD * CHID };
    ca.s[4] = { Wkn,  wknp, CCAD * CHID };
    ca.s[5] = { Wvn,  wvnp, CCAD * CHID };
    ca.s[6] = { enc,  encp, CB * CENCL * CCAD };
    cvt_multi<<<dim3(80, 7), 512>>>(ca);

    // 2) hidden conversion
    cvtf<<<512, 512>>>(hidden, hidp, GM * GK);

    // 3) K/V/KN/VN projections -> g_kv fp32
    proj_f16<<<dim3(CB, CHID / 128, 4), 512, PROJ_SMEM>>>();

    // 4) Q = hidden @ Wq
    gemm_f16<<<dim3(GM / 128, GN / 256), 512, GEMM_SMEM>>>(hidp, wqp, nullptr, qp);

    // 5) attention
    qattn_lite<<<dim3(CB * (CHW / 64), CNH / 2), 256, sizeof(SmA)>>>(idx);

    // 6) out = attn @ Wout + bias   (launch #6 -> ncu -s 5 captures THIS)
    gemm_f16<<<dim3(GM / 128, GN / 256), 512, GEMM_SMEM>>>(atp, wop, bout, out);
}

// round 14
// speedup vs baseline: 1.1369x; 1.1369x over previous
#include <cuda_runtime.h>
#include <cuda_fp16.h>
#include <cstdint>

#define CB    2
#define CHW   4096
#define CHID  1280
#define CCAD  2048
#define CLTXT 77
#define CNT   4
#define CNH   20
#define CENCL (CLTXT + CNT)

#define GM 8192
#define GK 1280
#define GN 1280
#define CBSZ (CB * 80 * CHID)

// ---------------- scratch (device globals) ----------------
__device__ float g_q[(size_t)GM * GK];
__device__ float g_kv[(size_t)4 * CBSZ];
__device__ __half g_hid[(size_t)GM * GK];
__device__ __half g_wq[(size_t)GK * GN];
__device__ __half g_wo[(size_t)GK * GN];
__device__ __half g_attn[(size_t)GM * GK];
__device__ __half g_enc[(size_t)CB * CENCL * CCAD];
__device__ __half g_wk [(size_t)CCAD * CHID];
__device__ __half g_wv [(size_t)CCAD * CHID];
__device__ __half g_wkn[(size_t)CCAD * CHID];
__device__ __half g_wvn[(size_t)CCAD * CHID];

// =====================================================================
// fp32 -> fp16 converts: ALL segments in one launch
// =====================================================================
struct CvtSeg { const float* src; __half* dst; int len; };
struct CvtArgs { CvtSeg s[8]; };

__global__ __launch_bounds__(512) void cvt_multi(CvtArgs a)
{
    const CvtSeg seg = a.s[blockIdx.y];
    const float* __restrict__ x = seg.src;
    __half* __restrict__ y = seg.dst;
    for (int i = (blockIdx.x * 512 + threadIdx.x) * 4; i < seg.len; i += gridDim.x * 512 * 4) {
        const float4 v = *(const float4*)(x + i);
        *(__half2*)(y + i)     = __floats2half2_rn(v.x, v.y);
        *(__half2*)(y + i + 2) = __floats2half2_rn(v.z, v.w);
    }
}

// =====================================================================
// shared mma helpers
// =====================================================================
#define CP_ASYNC(dst, src) asm volatile("cp.async.cg.shared.global [%0], [%1], 16;" :: "r"(dst), "l"(src))
#define CP_ASYNC_Z(dst, src, ok) asm volatile("cp.async.cg.shared.global [%0], [%1], 16, %2;" :: "r"(dst), "l"(src), "r"((ok) ? 16 : 0))

__device__ __forceinline__ void ldsm4(uint32_t* r, uint32_t a) {
    asm volatile("ldmatrix.sync.aligned.m8n8.x4.shared.b16 {%0,%1,%2,%3}, [%4];"
        : "=r"(r[0]), "=r"(r[1]), "=r"(r[2]), "=r"(r[3]) : "r"(a));
}
__device__ __forceinline__ void ldsm4t(uint32_t* r, uint32_t a) {
    asm volatile("ldmatrix.sync.aligned.m8n8.x4.trans.shared.b16 {%0,%1,%2,%3}, [%4];"
        : "=r"(r[0]), "=r"(r[1]), "=r"(r[2]), "=r"(r[3]) : "r"(a));
}
__device__ __forceinline__ void mma16816(float* c, const uint32_t* a, const uint32_t* b) {
    asm volatile("mma.sync.aligned.m16n8k16.row.col.f32.f16.f16.f32 "
        "{%0,%1,%2,%3}, {%4,%5,%6,%7}, {%8,%9}, {%0,%1,%2,%3};"
        : "+f"(c[0]), "+f"(c[1]), "+f"(c[2]), "+f"(c[3])
        : "r"(a[0]), "r"(a[1]), "r"(a[2]), "r"(a[3]), "r"(b[0]), "r"(b[1]));
}

#define A_PITCH 40
#define ABUF (128 * A_PITCH)
#define NSTAGE 4
#define PB_PITCH 136
#define PBUF (32 * PB_PITCH)
#define PROJ_SMEM ((NSTAGE * ABUF + NSTAGE * PBUF) * 2)
#define GB_PITCH 264
#define GBUF (32 * GB_PITCH)
#define GEMM_SMEM ((NSTAGE * ABUF + NSTAGE * GBUF) * 2)

// =====================================================================
// fp16 mma.sync GEMM v5: CTA 128x256, 512 thr / 16 warps (4x4), wt 32x64
// =====================================================================
__global__ __launch_bounds__(512, 1) void gemm_f16(
    const __half* __restrict__ A, const __half* __restrict__ B,
    const float* __restrict__ bias, float* __restrict__ C)
{
    extern __shared__ __align__(16) char sm[];
    __half* sA = (__half*)sm;
    __half* sB = sA + NSTAGE * ABUF;

    const int tid = threadIdx.x;
    const int m0 = blockIdx.x * 128, n0 = blockIdx.y * 256;
    const int lane = tid & 31, warp = tid >> 5;
    const int wm = warp & 3, wn = warp >> 2;

    const int arow = tid >> 2, ak8 = (tid & 3) << 3;
    const int brow = tid >> 5, bn8 = (tid & 31) << 3;
    const __half* gA = A + (size_t)(m0 + arow) * GK + ak8;
    const __half* gB = B + (size_t)brow * GN + n0 + bn8;
    const uint32_t dA = (uint32_t)__cvta_generic_to_shared(sA) + (uint32_t)(arow * A_PITCH + ak8) * 2;
    const uint32_t dB = (uint32_t)__cvta_generic_to_shared(sB) + (uint32_t)(brow * GB_PITCH + bn8) * 2;

#define LOADK(stage, kt) do {                                                   \
        const uint32_t ao_ = (uint32_t)(stage) * (ABUF * 2);                    \
        const uint32_t bo_ = (uint32_t)(stage) * (GBUF * 2);                    \
        const size_t ka_ = (size_t)(kt) * 32;                                   \
        CP_ASYNC(dA + ao_, gA + ka_);                                           \
        CP_ASYNC(dB + bo_,                     gB + ka_ * GN);                  \
        CP_ASYNC(dB + bo_ + 16 * GB_PITCH * 2, gB + (ka_ + 16) * GN);           \
        asm volatile("cp.async.commit_group;");                                 \
    } while (0)

    LOADK(0, 0);
    LOADK(1, 1);
    LOADK(2, 2);

    float acc[2][8][4] = {};

    const uint32_t aOff = (uint32_t)((wm * 32 + (lane & 15)) * A_PITCH + ((lane >> 4) << 3)) * 2;
    const uint32_t aB0 = (uint32_t)__cvta_generic_to_shared(sA) + aOff;
    const uint32_t bOff = (uint32_t)(((lane & 7) + ((lane >> 3) & 1) * 8) * GB_PITCH
                                     + wn * 64 + ((lane >> 4) << 3)) * 2;
    const uint32_t bB0 = (uint32_t)__cvta_generic_to_shared(sB) + bOff;

    const int NKT = GK / 32;   // 40
    for (int kt = 0; kt < NKT; kt++) {
        const int s = kt & (NSTAGE - 1);
        if (kt < NKT - 2)       asm volatile("cp.async.wait_group 2;");
        else if (kt == NKT - 2) asm volatile("cp.async.wait_group 1;");
        else                    asm volatile("cp.async.wait_group 0;");
        __syncthreads();

        const uint32_t ah = aB0 + s * (ABUF * 2);
        const uint32_t bh = bB0 + s * (GBUF * 2);
#pragma unroll
        for (int ks = 0; ks < 2; ks++) {
            const uint32_t ka = ah + ks * 32;
            const uint32_t kb = bh + ks * (16 * GB_PITCH * 2);
            uint32_t A0[4], A1[4];
            ldsm4(A0, ka);
            ldsm4(A1, ka + 16 * A_PITCH * 2);
            uint32_t Bf[16];
#pragma unroll
            for (int t = 0; t < 4; t++) ldsm4t(Bf + t * 4, kb + t * 32);
#pragma unroll
            for (int j = 0; j < 8; j++) {
                mma16816(acc[0][j], A0, &Bf[j * 2]);
                mma16816(acc[1][j], A1, &Bf[j * 2]);
            }
        }
        if (kt + 3 < NKT) {
            LOADK((kt + 3) & (NSTAGE - 1), kt + 3);
        }
    }

#pragma unroll
    for (int f = 0; f < 2; f++) {
        const int r0 = m0 + wm * 32 + f * 16 + (lane >> 2);
#pragma unroll
        for (int j = 0; j < 8; j++) {
            const int cc = n0 + wn * 64 + j * 8 + ((lane & 3) << 1);
            float b0 = 0.f, b1 = 0.f;
            if (bias) { b0 = bias[cc]; b1 = bias[cc + 1]; }
            *(float2*)(C + (size_t)r0 * GN + cc) =
                make_float2(acc[f][j][0] + b0, acc[f][j][1] + b1);
            *(float2*)(C + (size_t)(r0 + 8) * GN + cc) =
                make_float2(acc[f][j][2] + b0, acc[f][j][3] + b1);
        }
    }
#undef LOADK
}

// =====================================================================
// fp16 projection GEMM, masked M (K/V/KN/VN -> g_kv fp32), CTA 128x128
// =====================================================================
__global__ __launch_bounds__(512, 1) void proj_f16()
{
    extern __shared__ __align__(16) char sm[];
    __half* sA = (__half*)sm;
    __half* sB = sA + NSTAGE * ABUF;

    const int tid = threadIdx.x;
    const int b = blockIdx.x, n0 = blockIdx.y * 128, type = blockIdx.z;
    const int M = (type < 2) ? CLTXT : CNT;
    const __half* Asrc = g_enc + (size_t)b * CENCL * CCAD + ((type >= 2) ? (size_t)CLTXT * CCAD : 0);
    const __half* Bsrc = (type == 0) ? g_wk : (type == 1) ? g_wv : (type == 2) ? g_wkn : g_wvn;
    float* C = g_kv + (size_t)type * CBSZ + (size_t)b * 80 * CHID;

    const int lane = tid & 31, warp = tid >> 5;
    const int wm = warp >> 2, wn = warp & 3;

    const int arow = tid >> 2, ak8 = (tid & 3) << 3;
    const int brow = tid >> 4, bn8 = (tid & 15) << 3;
    const bool aok = arow < M;
    const __half* gA = Asrc + (size_t)arow * CCAD + ak8;
    const __half* gB = Bsrc + (size_t)brow * CHID + n0 + bn8;
    const uint32_t dA = (uint32_t)__cvta_generic_to_shared(sA) + (uint32_t)(arow * A_PITCH + ak8) * 2;
    const uint32_t dB = (uint32_t)__cvta_generic_to_shared(sB) + (uint32_t)(brow * PB_PITCH + bn8) * 2;

#define LOADKP(stage, kt) do {                                                  \
        const uint32_t ao_ = (uint32_t)(stage) * (ABUF * 2);                    \
        const uint32_t bo_ = (uint32_t)(stage) * (PBUF * 2);                    \
        const size_t kofs_ = (size_t)(kt) * 32;                                 \
        CP_ASYNC_Z(dA + ao_, gA + kofs_, aok);                                  \
        CP_ASYNC(dB + bo_, gB + kofs_ * CHID);                                  \
        asm volatile("cp.async.commit_group;");                                 \
    } while (0)

    LOADKP(0, 0);
    LOADKP(1, 1);
    LOADKP(2, 2);

    float acc[2][4][4] = {};

    const uint32_t aOff = (uint32_t)((wm * 32 + (lane & 15)) * A_PITCH + ((lane >> 4) << 3)) * 2;
    const uint32_t aB0 = (uint32_t)__cvta_generic_to_shared(sA) + aOff;
    const uint32_t bOff = (uint32_t)(((lane & 7) + ((lane >> 3) & 1) * 8) * PB_PITCH
                                     + wn * 32 + ((lane >> 4) << 3)) * 2;
    const uint32_t bB0 = (uint32_t)__cvta_generic_to_shared(sB) + bOff;

    const int NKT = CCAD / 32;   // 64
    for (int kt = 0; kt < NKT; kt++) {
        const int s = kt & (NSTAGE - 1);
        if (kt < NKT - 2)       asm volatile("cp.async.wait_group 2;");
        else if (kt == NKT - 2) asm volatile("cp.async.wait_group 1;");
        else                    asm volatile("cp.async.wait_group 0;");
        __syncthreads();

        const uint32_t ah = aB0 + s * (ABUF * 2);
        const uint32_t bh = bB0 + s * (PBUF * 2);
#pragma unroll
        for (int ks = 0; ks < 2; ks++) {
            const uint32_t ka = ah + ks * 32;
            const uint32_t kb = bh + ks * (16 * PB_PITCH * 2);
            uint32_t A0[4], A1[4];
            ldsm4(A0, ka);
            ldsm4(A1, ka + 16 * A_PITCH * 2);
            uint32_t Bf[8];
            ldsm4t(Bf,     kb);
            ldsm4t(Bf + 4, kb + 32);
#pragma unroll
            for (int j = 0; j < 4; j++) {
                mma16816(acc[0][j], A0, &Bf[j * 2]);
                mma16816(acc[1][j], A1, &Bf[j * 2]);
            }
        }
        if (kt + 3 < NKT) {
            LOADKP((kt + 3) & (NSTAGE - 1), kt + 3);
        }
    }

#pragma unroll
    for (int fm = 0; fm < 2; fm++) {
        const int r0 = wm * 32 + fm * 16 + (lane >> 2);
#pragma unroll
        for (int j = 0; j < 4; j++) {
            const int cc = n0 + wn * 32 + j * 8 + ((lane & 3) << 1);
            if (r0 < M)
                *(float2*)(C + (size_t)r0 * CHID + cc) =
                    make_float2(acc[fm][j][0], acc[fm][j][1]);
            if (r0 + 8 < M)
                *(float2*)(C + (size_t)(r0 + 8) * CHID + cc) =
                    make_float2(acc[fm][j][2], acc[fm][j][3]);
        }
    }
#undef LOADKP
}

// =====================================================================
// Attention v3: fp16 K/V staging (fp32 math), 2 CTAs/SM
// =====================================================================
struct SmA {
    float  Qs[2][64][68];        // fp32, 34816 B
    __half Ks[2][CLTXT][68];     // 20944 B
    __half Vs[2][CLTXT][68];     // 20944 B
    __half KNs[2][CNT][68];      // 1088 B
    __half VNs[2][CNT][68];      // 1088 B
    float  Wbuf[8][8][80];       // 20480 B
};                               // ~97 KB -> 2 CTAs/SM

__global__ __launch_bounds__(256) void qattn_lite(const int* __restrict__ idx_alter)
{
    extern __shared__ char raw[];
    SmA& S = *reinterpret_cast<SmA*>(raw);
    const int b  = blockIdx.x >> 6;
    const int t0 = (blockIdx.x & 63) << 6;
    const int h0 = blockIdx.y * 2;
    const int tid = threadIdx.x;

    for (int i = tid; i < 64 * 32; i += 256) {
        const int t = i >> 5, c4 = (i & 31) << 2;
        const int hh = c4 >> 6, d = c4 & 63;
        float4 q = *(const float4*)(g_q + ((size_t)b * CHW + t0 + t) * CHID + h0 * 64 + c4);
        q.x *= 0.125f; q.y *= 0.125f; q.z *= 0.125f; q.w *= 0.125f;
        *(float4*)&S.Qs[hh][t][d] = q;
    }

    // stage K/V (fp32 gmem -> fp16 smem)
#pragma unroll
    for (int hh = 0; hh < 2; hh++) {
        const size_t cb = (size_t)(h0 + hh) * 64;
        const float* kK = g_kv + (size_t)0 * CBSZ + (size_t)b * 80 * CHID + cb;
        const float* kV = g_kv + (size_t)1 * CBSZ + (size_t)b * 80 * CHID + cb;
        for (int i = tid; i < CLTXT * 16; i += 256) {
            const int j = i >> 4, d4 = (i & 15) << 2;
            const float4 k4 = *(const float4*)(kK + (size_t)j * CHID + d4);
            const float4 v4 = *(const float4*)(kV + (size_t)j * CHID + d4);
            __half2 kh0 = __floats2half2_rn(k4.x, k4.y), kh1 = __floats2half2_rn(k4.z, k4.w);
            __half2 vh0 = __floats2half2_rn(v4.x, v4.y), vh1 = __floats2half2_rn(v4.z, v4.w);
            *(__half2*)&S.Ks[hh][j][d4]     = kh0;
            *(__half2*)&S.Ks[hh][j][d4 + 2] = kh1;
            *(__half2*)&S.Vs[hh][j][d4]     = vh0;
            *(__half2*)&S.Vs[hh][j][d4 + 2] = vh1;
        }
        const float* kKN = g_kv + (size_t)2 * CBSZ + (size_t)b * 80 * CHID + cb;
        const float* kVN = g_kv + (size_t)3 * CBSZ + (size_t)b * 80 * CHID + cb;
        for (int i = tid; i < CNT * 16; i += 256) {
            const int j = i >> 4, d4 = (i & 15) << 2;
            const float4 k4 = *(const float4*)(kKN + (size_t)j * CHID + d4);
            const float4 v4 = *(const float4*)(kVN + (size_t)j * CHID + d4);
            *(__half2*)&S.KNs[hh][j][d4]     = __floats2half2_rn(k4.x, k4.y);
            *(__half2*)&S.KNs[hh][j][d4 + 2] = __floats2half2_rn(k4.z, k4.w);
            *(__half2*)&S.VNs[hh][j][d4]     = __floats2half2_rn(v4.x, v4.y);
            *(__half2*)&S.VNs[hh][j][d4 + 2] = __floats2half2_rn(v4.z, v4.w);
        }
    }
    const int sidx = idx_alter[b];
    __syncthreads();

    const int warp = tid >> 5, lane = tid & 31;
    const int j0 = lane, j1 = lane + 32, j2 = lane + 64;
    const bool j2ok = (j2 < CLTXT);
    const int j2c = j2ok ? j2 : 0;
    const int d0 = lane << 1;

#pragma unroll
    for (int hh = 0; hh < 2; hh++) {
        const __half* k0p = S.Ks[hh][j0];
        const __half* k1p = S.Ks[hh][j1];
        const __half* k2p = S.Ks[hh][j2c];
        const __half* knp = S.KNs[hh][lane & 3];

        float l0[8], l1[8], l2[8], ln[8];
#pragma unroll
        for (int it = 0; it < 8; it++) { l0[it] = l1[it] = l2[it] = ln[it] = 0.f; }

#pragma unroll 4
        for (int d4 = 0; d4 < 64; d4 += 4) {
            const __half2 xh0 = *(const __half2*)(k0p + d4), xh1 = *(const __half2*)(k0p + d4 + 2);
            const __half2 yh0 = *(const __half2*)(k1p + d4), yh1 = *(const __half2*)(k1p + d4 + 2);
            const __half2 zh0 = *(const __half2*)(k2p + d4), zh1 = *(const __half2*)(k2p + d4 + 2);
            const __half2 wh0 = *(const __half2*)(knp + d4), wh1 = *(const __half2*)(knp + d4 + 2);
            const float2 x0 = __half22float2(xh0), x1 = __half22float2(xh1);
            const float2 y0 = __half22float2(yh0), y1 = __half22float2(yh1);
            const float2 z0 = __half22float2(zh0), z1 = __half22float2(zh1);
            const float2 w0 = __half22float2(wh0), w1 = __half22float2(wh1);
#pragma unroll
            for (int it = 0; it < 8; it++) {
                const float4 q = *(const float4*)(&S.Qs[hh][warp * 8 + it][d4]);
                l0[it] += q.x * x0.x + q.y * x0.y + q.z * x1.x + q.w * x1.y;
                l1[it] += q.x * y0.x + q.y * y0.y + q.z * y1.x + q.w * y1.y;
                l2[it] += q.x * z0.x + q.y * z0.y + q.z * z1.x + q.w * z1.y;
                ln[it] += q.x * w0.x + q.y * w0.y + q.z * w1.x + q.w * w1.y;
            }
        }

        const float2 vsel = __half22float2(*(const __half2*)&S.Vs[hh][sidx][d0]);
        const float2 a0v = __half22float2(*(const __half2*)&S.VNs[hh][0][d0]);
        const float2 a1v = __half22float2(*(const __half2*)&S.VNs[hh][1][d0]);
        const float2 a2v = __half22float2(*(const __half2*)&S.VNs[hh][2][d0]);
        const float2 a3v = __half22float2(*(const __half2*)&S.VNs[hh][3][d0]);
        float vix[8], viy[8];
#pragma unroll
        for (int it = 0; it < 8; it++) {
            const float a0 = l0[it], a1 = l1[it];
            const float a2 = j2ok ? l2[it] : -1e30f;
            float lm = fmaxf(fmaxf(a0, a1), a2);
#pragma unroll
            for (int o = 16; o; o >>= 1) lm = fmaxf(lm, __shfl_xor_sync(0xffffffffu, lm, o));
            const float e0 = __expf(a0 - lm);
            const float e1 = __expf(a1 - lm);
            const float e2 = j2ok ? __expf(a2 - lm) : 0.f;
            float es = e0 + e1 + e2;
#pragma unroll
            for (int o = 16; o; o >>= 1) es += __shfl_xor_sync(0xffffffffu, es, o);
            const float inv = 1.f / es;
            float* wrow = S.Wbuf[warp][it];
            wrow[j0] = e0 * inv;
            wrow[j1] = e1 * inv;
            if (j2ok) wrow[j2] = e2 * inv;

            float lnv = (lane < CNT) ? ln[it] : -1e30f;
            float mn = lnv;
            mn = fmaxf(mn, __shfl_xor_sync(0xffffffffu, mn, 1));
            mn = fmaxf(mn, __shfl_xor_sync(0xffffffffu, mn, 2));
            const float en = __expf(lnv - mn);
            float sn = en;
            sn += __shfl_xor_sync(0xffffffffu, sn, 1);
            sn += __shfl_xor_sync(0xffffffffu, sn, 2);
            const float wnv = en / sn;
            const float wn0 = __shfl_sync(0xffffffffu, wnv, 0);
            const float wn1 = __shfl_sync(0xffffffffu, wnv, 1);
            const float wn2 = __shfl_sync(0xffffffffu, wnv, 2);
            const float wn3 = __shfl_sync(0xffffffffu, wnv, 3);
            vix[it] = wn0 * a0v.x + wn1 * a1v.x + wn2 * a2v.x + wn3 * a3v.x;
            viy[it] = wn0 * a0v.y + wn1 * a1v.y + wn2 * a2v.y + wn3 * a3v.y;
        }
        __syncwarp();

        float bx[8], by[8];
#pragma unroll
        for (int it = 0; it < 8; it++) { bx[it] = 0.f; by[it] = 0.f; }
#pragma unroll 7
        for (int j = 0; j < CLTXT; j++) {
            const float2 vv = __half22float2(*(const __half2*)&S.Vs[hh][j][d0]);
#pragma unroll
            for (int it = 0; it < 8; it++) {
                const float wj = S.Wbuf[warp][it][j];
                bx[it] += wj * vv.x;
                by[it] += wj * vv.y;
            }
        }

#pragma unroll
        for (int it = 0; it < 8; it++) {
            const float wsel = S.Wbuf[warp][it][sidx];
            const float ox = bx[it] + wsel * (vix[it] - vsel.x);
            const float oy = by[it] + wsel * (viy[it] - vsel.y);
            const int t = warp * 8 + it;
            const size_t off = ((size_t)b * CHW + t0 + t) * CHID + (h0 + hh) * 64 + d0;
            *(__half2*)(g_attn + off) = __floats2half2_rn(ox, oy);
        }
        __syncwarp();
    }
}

// ---------------- launch ----------------
extern "C" void kernel_launch(void* const* d_in, const int* in_sizes, int n_in,
                              void* d_out, int out_size)
{
    (void)in_sizes; (void)n_in; (void)out_size;
    const float* hidden = (const float*)d_in[0];
    const float* enc    = (const float*)d_in[1];
    const int*   idx    = (const int*)  d_in[2];
    const float* Wq     = (const float*)d_in[3];
    const float* Wk     = (const float*)d_in[4];
    const float* Wv     = (const float*)d_in[5];
    const float* Wkn    = (const float*)d_in[6];
    const float* Wvn    = (const float*)d_in[7];
    const float* Wout   = (const float*)d_in[8];
    const float* bout   = (const float*)d_in[9];
    float* out = (float*)d_out;

    __half *hidp, *wqp, *wop, *atp, *encp, *wkp, *wvp, *wknp, *wvnp;
    float* qp;
    cudaGetSymbolAddress((void**)&hidp, g_hid);
    cudaGetSymbolAddress((void**)&wqp,  g_wq);
    cudaGetSymbolAddress((void**)&wop,  g_wo);
    cudaGetSymbolAddress((void**)&atp,  g_attn);
    cudaGetSymbolAddress((void**)&encp, g_enc);
    cudaGetSymbolAddress((void**)&wkp,  g_wk);
    cudaGetSymbolAddress((void**)&wvp,  g_wv);
    cudaGetSymbolAddress((void**)&wknp, g_wkn);
    cudaGetSymbolAddress((void**)&wvnp, g_wvn);
    cudaGetSymbolAddress((void**)&qp,   g_q);

    cudaFuncSetAttribute(gemm_f16, cudaFuncAttributeMaxDynamicSharedMemorySize, GEMM_SMEM);
    cudaFuncSetAttribute(proj_f16, cudaFuncAttributeMaxDynamicSharedMemorySize, PROJ_SMEM);
    cudaFuncSetAttribute(qattn_lite, cudaFuncAttributeMaxDynamicSharedMemorySize, (int)sizeof(SmA));

    // 1) ALL conversions, one launch (8 segments)
    CvtArgs ca;
    ca.s[0] = { hidden, hidp, GM * GK };
    ca.s[1] = { Wq,   wqp,  GK * GN };
    ca.s[2] = { Wout, wop,  GK * GN };
    ca.s[3] = { Wk,   wkp,  CCAD * CHID };
    ca.s[4] = { Wv,   wvp,  CCAD * CHID };
    ca.s[5] = { Wkn,  wknp, CCAD * CHID };
    ca.s[6] = { Wvn,  wvnp, CCAD * CHID };
    ca.s[7] = { enc,  encp, CB * CENCL * CCAD };
    cvt_multi<<<dim3(160, 8), 512>>>(ca);

    // 2) K/V/KN/VN projections -> g_kv fp32
    proj_f16<<<dim3(CB, CHID / 128, 4), 512, PROJ_SMEM>>>();

    // 3) Q = hidden @ Wq
    gemm_f16<<<dim3(GM / 128, GN / 256), 512, GEMM_SMEM>>>(hidp, wqp, nullptr, qp);

    // 4) attention
    qattn_lite<<<dim3(CB * (CHW / 64), CNH / 2), 256, sizeof(SmA)>>>(idx);

    // 5) out = attn @ Wout + bias
    gemm_f16<<<dim3(GM / 128, GN / 256), 512, GEMM_SMEM>>>(atp, wop, bout, out);
}

// round 15
// speedup vs baseline: 1.4041x; 1.2351x over previous
#include <cuda_runtime.h>
#include <cuda_fp16.h>
#include <cstdint>

#define CB    2
#define CHW   4096
#define CHID  1280
#define CCAD  2048
#define CLTXT 77
#define CNT   4
#define CNH   20
#define CENCL (CLTXT + CNT)

#define GM 8192
#define GK 1280
#define GN 1280
#define CBSZ (CB * 80 * CHID)

// ---------------- scratch (device globals) ----------------
__device__ float g_q[(size_t)GM * GK];
__device__ float g_kv[(size_t)4 * CBSZ];
__device__ __half g_hid[(size_t)GM * GK];
__device__ __half g_wq[(size_t)GK * GN];
__device__ __half g_wo[(size_t)GK * GN];
__device__ __half g_attn[(size_t)GM * GK];
__device__ __half g_enc[(size_t)CB * CENCL * CCAD];
__device__ __half g_wk [(size_t)CCAD * CHID];
__device__ __half g_wv [(size_t)CCAD * CHID];
__device__ __half g_wkn[(size_t)CCAD * CHID];
__device__ __half g_wvn[(size_t)CCAD * CHID];

// =====================================================================
// fp32 -> fp16 converts: ALL segments in one launch
// =====================================================================
struct CvtSeg { const float* src; __half* dst; int len; };
struct CvtArgs { CvtSeg s[8]; };

__global__ __launch_bounds__(512) void cvt_multi(CvtArgs a)
{
    const CvtSeg seg = a.s[blockIdx.y];
    const float* __restrict__ x = seg.src;
    __half* __restrict__ y = seg.dst;
    for (int i = (blockIdx.x * 512 + threadIdx.x) * 4; i < seg.len; i += gridDim.x * 512 * 4) {
        const float4 v = *(const float4*)(x + i);
        *(__half2*)(y + i)     = __floats2half2_rn(v.x, v.y);
        *(__half2*)(y + i + 2) = __floats2half2_rn(v.z, v.w);
    }
}

// =====================================================================
// shared mma helpers
// =====================================================================
#define CP_ASYNC(dst, src) asm volatile("cp.async.cg.shared.global [%0], [%1], 16;" :: "r"(dst), "l"(src))
#define CP_ASYNC_Z(dst, src, ok) asm volatile("cp.async.cg.shared.global [%0], [%1], 16, %2;" :: "r"(dst), "l"(src), "r"((ok) ? 16 : 0))

__device__ __forceinline__ void ldsm4(uint32_t* r, uint32_t a) {
    asm volatile("ldmatrix.sync.aligned.m8n8.x4.shared.b16 {%0,%1,%2,%3}, [%4];"
        : "=r"(r[0]), "=r"(r[1]), "=r"(r[2]), "=r"(r[3]) : "r"(a));
}
__device__ __forceinline__ void ldsm4t(uint32_t* r, uint32_t a) {
    asm volatile("ldmatrix.sync.aligned.m8n8.x4.trans.shared.b16 {%0,%1,%2,%3}, [%4];"
        : "=r"(r[0]), "=r"(r[1]), "=r"(r[2]), "=r"(r[3]) : "r"(a));
}
__device__ __forceinline__ void mma16816(float* c, const uint32_t* a, const uint32_t* b) {
    asm volatile("mma.sync.aligned.m16n8k16.row.col.f32.f16.f16.f32 "
        "{%0,%1,%2,%3}, {%4,%5,%6,%7}, {%8,%9}, {%0,%1,%2,%3};"
        : "+f"(c[0]), "+f"(c[1]), "+f"(c[2]), "+f"(c[3])
        : "r"(a[0]), "r"(a[1]), "r"(a[2]), "r"(a[3]), "r"(b[0]), "r"(b[1]));
}

#define A_PITCH 40
#define ABUF (128 * A_PITCH)
#define NSTAGE 4
#define PB_PITCH 136
#define PBUF (32 * PB_PITCH)
#define PROJ_SMEM ((NSTAGE * ABUF + NSTAGE * PBUF) * 2)
#define GB_PITCH 264
#define GBUF (32 * GB_PITCH)
#define GEMM_SMEM ((NSTAGE * ABUF + NSTAGE * GBUF) * 2)

// =====================================================================
// fp16 mma.sync GEMM: CTA 128x256, 512 thr / 16 warps (4x4), wt 32x64
// =====================================================================
__global__ __launch_bounds__(512, 1) void gemm_f16(
    const __half* __restrict__ A, const __half* __restrict__ B,
    const float* __restrict__ bias, float* __restrict__ C)
{
    extern __shared__ __align__(16) char sm[];
    __half* sA = (__half*)sm;
    __half* sB = sA + NSTAGE * ABUF;

    const int tid = threadIdx.x;
    const int m0 = blockIdx.x * 128, n0 = blockIdx.y * 256;
    const int lane = tid & 31, warp = tid >> 5;
    const int wm = warp & 3, wn = warp >> 2;

    const int arow = tid >> 2, ak8 = (tid & 3) << 3;
    const int brow = tid >> 5, bn8 = (tid & 31) << 3;
    const __half* gA = A + (size_t)(m0 + arow) * GK + ak8;
    const __half* gB = B + (size_t)brow * GN + n0 + bn8;
    const uint32_t dA = (uint32_t)__cvta_generic_to_shared(sA) + (uint32_t)(arow * A_PITCH + ak8) * 2;
    const uint32_t dB = (uint32_t)__cvta_generic_to_shared(sB) + (uint32_t)(brow * GB_PITCH + bn8) * 2;

#define LOADK(stage, kt) do {                                                   \
        const uint32_t ao_ = (uint32_t)(stage) * (ABUF * 2);                    \
        const uint32_t bo_ = (uint32_t)(stage) * (GBUF * 2);                    \
        const size_t ka_ = (size_t)(kt) * 32;                                   \
        CP_ASYNC(dA + ao_, gA + ka_);                                           \
        CP_ASYNC(dB + bo_,                     gB + ka_ * GN);                  \
        CP_ASYNC(dB + bo_ + 16 * GB_PITCH * 2, gB + (ka_ + 16) * GN);           \
        asm volatile("cp.async.commit_group;");                                 \
    } while (0)

    LOADK(0, 0);
    LOADK(1, 1);
    LOADK(2, 2);

    float acc[2][8][4] = {};

    const uint32_t aOff = (uint32_t)((wm * 32 + (lane & 15)) * A_PITCH + ((lane >> 4) << 3)) * 2;
    const uint32_t aB0 = (uint32_t)__cvta_generic_to_shared(sA) + aOff;
    const uint32_t bOff = (uint32_t)(((lane & 7) + ((lane >> 3) & 1) * 8) * GB_PITCH
                                     + wn * 64 + ((lane >> 4) << 3)) * 2;
    const uint32_t bB0 = (uint32_t)__cvta_generic_to_shared(sB) + bOff;

    const int NKT = GK / 32;   // 40
    for (int kt = 0; kt < NKT; kt++) {
        const int s = kt & (NSTAGE - 1);
        if (kt < NKT - 2)       asm volatile("cp.async.wait_group 2;");
        else if (kt == NKT - 2) asm volatile("cp.async.wait_group 1;");
        else                    asm volatile("cp.async.wait_group 0;");
        __syncthreads();

        const uint32_t ah = aB0 + s * (ABUF * 2);
        const uint32_t bh = bB0 + s * (GBUF * 2);
#pragma unroll
        for (int ks = 0; ks < 2; ks++) {
            const uint32_t ka = ah + ks * 32;
            const uint32_t kb = bh + ks * (16 * GB_PITCH * 2);
            uint32_t A0[4], A1[4];
            ldsm4(A0, ka);
            ldsm4(A1, ka + 16 * A_PITCH * 2);
            uint32_t Bf[16];
#pragma unroll
            for (int t = 0; t < 4; t++) ldsm4t(Bf + t * 4, kb + t * 32);
#pragma unroll
            for (int j = 0; j < 8; j++) {
                mma16816(acc[0][j], A0, &Bf[j * 2]);
                mma16816(acc[1][j], A1, &Bf[j * 2]);
            }
        }
        if (kt + 3 < NKT) {
            LOADK((kt + 3) & (NSTAGE - 1), kt + 3);
        }
    }

#pragma unroll
    for (int f = 0; f < 2; f++) {
        const int r0 = m0 + wm * 32 + f * 16 + (lane >> 2);
#pragma unroll
        for (int j = 0; j < 8; j++) {
            const int cc = n0 + wn * 64 + j * 8 + ((lane & 3) << 1);
            float b0 = 0.f, b1 = 0.f;
            if (bias) { b0 = bias[cc]; b1 = bias[cc + 1]; }
            *(float2*)(C + (size_t)r0 * GN + cc) =
                make_float2(acc[f][j][0] + b0, acc[f][j][1] + b1);
            *(float2*)(C + (size_t)(r0 + 8) * GN + cc) =
                make_float2(acc[f][j][2] + b0, acc[f][j][3] + b1);
        }
    }
#undef LOADK
}

// =====================================================================
// fp16 projection GEMM, masked M (K/V/KN/VN -> g_kv fp32), CTA 128x128
// =====================================================================
__global__ __launch_bounds__(512, 1) void proj_f16()
{
    extern __shared__ __align__(16) char sm[];
    __half* sA = (__half*)sm;
    __half* sB = sA + NSTAGE * ABUF;

    const int tid = threadIdx.x;
    const int b = blockIdx.x, n0 = blockIdx.y * 128, type = blockIdx.z;
    const int M = (type < 2) ? CLTXT : CNT;
    const __half* Asrc = g_enc + (size_t)b * CENCL * CCAD + ((type >= 2) ? (size_t)CLTXT * CCAD : 0);
    const __half* Bsrc = (type == 0) ? g_wk : (type == 1) ? g_wv : (type == 2) ? g_wkn : g_wvn;
    float* C = g_kv + (size_t)type * CBSZ + (size_t)b * 80 * CHID;

    const int lane = tid & 31, warp = tid >> 5;
    const int wm = warp >> 2, wn = warp & 3;

    const int arow = tid >> 2, ak8 = (tid & 3) << 3;
    const int brow = tid >> 4, bn8 = (tid & 15) << 3;
    const bool aok = arow < M;
    const __half* gA = Asrc + (size_t)arow * CCAD + ak8;
    const __half* gB = Bsrc + (size_t)brow * CHID + n0 + bn8;
    const uint32_t dA = (uint32_t)__cvta_generic_to_shared(sA) + (uint32_t)(arow * A_PITCH + ak8) * 2;
    const uint32_t dB = (uint32_t)__cvta_generic_to_shared(sB) + (uint32_t)(brow * PB_PITCH + bn8) * 2;

#define LOADKP(stage, kt) do {                                                  \
        const uint32_t ao_ = (uint32_t)(stage) * (ABUF * 2);                    \
        const uint32_t bo_ = (uint32_t)(stage) * (PBUF * 2);                    \
        const size_t kofs_ = (size_t)(kt) * 32;                                 \
        CP_ASYNC_Z(dA + ao_, gA + kofs_, aok);                                  \
        CP_ASYNC(dB + bo_, gB + kofs_ * CHID);                                  \
        asm volatile("cp.async.commit_group;");                                 \
    } while (0)

    LOADKP(0, 0);
    LOADKP(1, 1);
    LOADKP(2, 2);

    float acc[2][4][4] = {};

    const uint32_t aOff = (uint32_t)((wm * 32 + (lane & 15)) * A_PITCH + ((lane >> 4) << 3)) * 2;
    const uint32_t aB0 = (uint32_t)__cvta_generic_to_shared(sA) + aOff;
    const uint32_t bOff = (uint32_t)(((lane & 7) + ((lane >> 3) & 1) * 8) * PB_PITCH
                                     + wn * 32 + ((lane >> 4) << 3)) * 2;
    const uint32_t bB0 = (uint32_t)__cvta_generic_to_shared(sB) + bOff;

    const int NKT = CCAD / 32;   // 64
    for (int kt = 0; kt < NKT; kt++) {
        const int s = kt & (NSTAGE - 1);
        if (kt < NKT - 2)       asm volatile("cp.async.wait_group 2;");
        else if (kt == NKT - 2) asm volatile("cp.async.wait_group 1;");
        else                    asm volatile("cp.async.wait_group 0;");
        __syncthreads();

        const uint32_t ah = aB0 + s * (ABUF * 2);
        const uint32_t bh = bB0 + s * (PBUF * 2);
#pragma unroll
        for (int ks = 0; ks < 2; ks++) {
            const uint32_t ka = ah + ks * 32;
            const uint32_t kb = bh + ks * (16 * PB_PITCH * 2);
            uint32_t A0[4], A1[4];
            ldsm4(A0, ka);
            ldsm4(A1, ka + 16 * A_PITCH * 2);
            uint32_t Bf[8];
            ldsm4t(Bf,     kb);
            ldsm4t(Bf + 4, kb + 32);
#pragma unroll
            for (int j = 0; j < 4; j++) {
                mma16816(acc[0][j], A0, &Bf[j * 2]);
                mma16816(acc[1][j], A1, &Bf[j * 2]);
            }
        }
        if (kt + 3 < NKT) {
            LOADKP((kt + 3) & (NSTAGE - 1), kt + 3);
        }
    }

#pragma unroll
    for (int fm = 0; fm < 2; fm++) {
        const int r0 = wm * 32 + fm * 16 + (lane >> 2);
#pragma unroll
        for (int j = 0; j < 4; j++) {
            const int cc = n0 + wn * 32 + j * 8 + ((lane & 3) << 1);
            if (r0 < M)
                *(float2*)(C + (size_t)r0 * CHID + cc) =
                    make_float2(acc[fm][j][0], acc[fm][j][1]);
            if (r0 + 8 < M)
                *(float2*)(C + (size_t)(r0 + 8) * CHID + cc) =
                    make_float2(acc[fm][j][2], acc[fm][j][3]);
        }
    }
#undef LOADKP
}

// =====================================================================
// Attention v4: FULL tensor-core path.
//   mma1: logits = Qf16 @ Kt  (64 tok x 88 keys, keys 80-83 = nested)
//   fragment softmax (txt cols 0-76, nested cols 80-83)
//   weight fold: col sidx -> 0, nested cols *= w_s
//   mma2: out = W' @ V'  (V' rows 0-76 txt, 80-83 nested, else 0)
// 8 warps: warp>>2 = head (2), warp&3 = 16-token group (4).
// =====================================================================
#define KT_PITCH 104    // halves; 208B rows -> conflict-free ldmatrix
#define V_PITCH  72     // halves; 144B rows

struct SmQ {
    __half Q[2][64][72];      // 18432 B  (fp16 scaled Q, row-major [tok][dim])
    __half Kt[2][64][KT_PITCH]; // 26624 B ([dim][key], keys 0-76 txt, 80-83 nest)
    __half V[2][96][V_PITCH];   // 27648 B ([key][dim], rows 77-79,84-95 zero)
};

__global__ __launch_bounds__(256, 2) void qattn_mma(const int* __restrict__ idx_alter)
{
    extern __shared__ __align__(16) char raw[];
    SmQ& S = *reinterpret_cast<SmQ*>(raw);
    const int b  = blockIdx.x >> 6;
    const int t0 = (blockIdx.x & 63) << 6;
    const int h0 = blockIdx.y * 2;
    const int tid = threadIdx.x;

    // ---- zero Kt and V (contiguous in struct) ----
    {
        int4* p = (int4*)&S.Kt[0][0][0];
        const int n16 = (int)((sizeof(S.Kt) + sizeof(S.V)) >> 4);
        for (int i = tid; i < n16; i += 256) p[i] = make_int4(0, 0, 0, 0);
    }
    __syncthreads();

    // ---- stage Q (fp32 -> fp16, scale 1/8 folded) ----
    for (int i = tid; i < 2048; i += 256) {
        const int h = i >> 10, rem = i & 1023;
        const int t = rem >> 4, d4 = (rem & 15) << 2;
        float4 q = *(const float4*)(g_q + ((size_t)b * CHW + t0 + t) * CHID + (h0 + h) * 64 + d4);
        *(__half2*)&S.Q[h][t][d4]     = __floats2half2_rn(q.x * 0.125f, q.y * 0.125f);
        *(__half2*)&S.Q[h][t][d4 + 2] = __floats2half2_rn(q.z * 0.125f, q.w * 0.125f);
    }

    // ---- stage K (transposed), KN, V, VN ----
#pragma unroll
    for (int hh = 0; hh < 2; hh++) {
        const size_t cb = (size_t)(h0 + hh) * 64 + (size_t)b * 80 * CHID;
        const float* kK  = g_kv + (size_t)0 * CBSZ + cb;
        const float* kV  = g_kv + (size_t)1 * CBSZ + cb;
        const float* kKN = g_kv + (size_t)2 * CBSZ + cb;
        const float* kVN = g_kv + (size_t)3 * CBSZ + cb;
        for (int i = tid; i < CLTXT * 16; i += 256) {
            const int j = i >> 4, d4 = (i & 15) << 2;
            const float4 k4 = *(const float4*)(kK + (size_t)j * CHID + d4);
            S.Kt[hh][d4 + 0][j] = __float2half(k4.x);
            S.Kt[hh][d4 + 1][j] = __float2half(k4.y);
            S.Kt[hh][d4 + 2][j] = __float2half(k4.z);
            S.Kt[hh][d4 + 3][j] = __float2half(k4.w);
            const float4 v4 = *(const float4*)(kV + (size_t)j * CHID + d4);
            *(__half2*)&S.V[hh][j][d4]     = __floats2half2_rn(v4.x, v4.y);
            *(__half2*)&S.V[hh][j][d4 + 2] = __floats2half2_rn(v4.z, v4.w);
        }
        for (int i = tid; i < CNT * 16; i += 256) {
            const int j = i >> 4, d4 = (i & 15) << 2;
            const float4 k4 = *(const float4*)(kKN + (size_t)j * CHID + d4);
            S.Kt[hh][d4 + 0][80 + j] = __float2half(k4.x);
            S.Kt[hh][d4 + 1][80 + j] = __float2half(k4.y);
            S.Kt[hh][d4 + 2][80 + j] = __float2half(k4.z);
            S.Kt[hh][d4 + 3][80 + j] = __float2half(k4.w);
            const float4 v4 = *(const float4*)(kVN + (size_t)j * CHID + d4);
            *(__half2*)&S.V[hh][80 + j][d4]     = __floats2half2_rn(v4.x, v4.y);
            *(__half2*)&S.V[hh][80 + j][d4 + 2] = __floats2half2_rn(v4.z, v4.w);
        }
    }
    const int sidx = idx_alter[b];
    __syncthreads();

    const int warp = tid >> 5, lane = tid & 31;
    const int h = warp >> 2;            // head within pair
    const int wtok = (warp & 3) << 4;   // 16-token group

    const uint32_t qbase = (uint32_t)__cvta_generic_to_shared(&S.Q[h][wtok][0])
        + (uint32_t)((lane & 15) * 72 + ((lane >> 4) << 3)) * 2;
    const uint32_t ktb = (uint32_t)__cvta_generic_to_shared(&S.Kt[h][0][0])
        + (uint32_t)(((lane & 7) + ((lane >> 3) & 1) * 8) * KT_PITCH + ((lane >> 4) << 3)) * 2;
    const uint32_t vb = (uint32_t)__cvta_generic_to_shared(&S.V[h][0][0])
        + (uint32_t)(((lane & 7) + ((lane >> 3) & 1) * 8) * V_PITCH + ((lane >> 4) << 3)) * 2;

    // ---- mma1: logits[16 tok][88 keys] ----
    float c[11][4] = {};
#pragma unroll
    for (int kc = 0; kc < 4; kc++) {
        uint32_t A[4];
        ldsm4(A, qbase + kc * 32);
        uint32_t Bf[24];
#pragma unroll
        for (int t = 0; t < 6; t++)
            ldsm4t(&Bf[t * 4], ktb + kc * (16 * KT_PITCH * 2) + t * 32);
#pragma unroll
        for (int f = 0; f < 11; f++) mma16816(c[f], A, &Bf[f * 2]);
    }

    // ---- fragment softmax (rows r = lane>>2 and r+8) ----
    const int colb = (lane & 3) << 1;
    float m0 = -1e30f, m1 = -1e30f;
#pragma unroll
    for (int f = 0; f < 10; f++) {
        const int col = f * 8 + colb;
        if (col < CLTXT)     { m0 = fmaxf(m0, c[f][0]); m1 = fmaxf(m1, c[f][2]); }
        if (col + 1 < CLTXT) { m0 = fmaxf(m0, c[f][1]); m1 = fmaxf(m1, c[f][3]); }
    }
    m0 = fmaxf(m0, __shfl_xor_sync(0xffffffffu, m0, 1));
    m0 = fmaxf(m0, __shfl_xor_sync(0xffffffffu, m0, 2));
    m1 = fmaxf(m1, __shfl_xor_sync(0xffffffffu, m1, 1));
    m1 = fmaxf(m1, __shfl_xor_sync(0xffffffffu, m1, 2));
    float s0 = 0.f, s1 = 0.f;
#pragma unroll
    for (int f = 0; f < 10; f++) {
        const int col = f * 8 + colb;
        c[f][0] = (col < CLTXT)     ? __expf(c[f][0] - m0) : 0.f;
        c[f][1] = (col + 1 < CLTXT) ? __expf(c[f][1] - m0) : 0.f;
        c[f][2] = (col < CLTXT)     ? __expf(c[f][2] - m1) : 0.f;
        c[f][3] = (col + 1 < CLTXT) ? __expf(c[f][3] - m1) : 0.f;
        s0 += c[f][0] + c[f][1];
        s1 += c[f][2] + c[f][3];
    }
    s0 += __shfl_xor_sync(0xffffffffu, s0, 1);
    s0 += __shfl_xor_sync(0xffffffffu, s0, 2);
    s1 += __shfl_xor_sync(0xffffffffu, s1, 1);
    s1 += __shfl_xor_sync(0xffffffffu, s1, 2);
    const float inv0 = 1.f / s0, inv1 = 1.f / s1;
#pragma unroll
    for (int f = 0; f < 10; f++) {
        c[f][0] *= inv0; c[f][1] *= inv0;
        c[f][2] *= inv1; c[f][3] *= inv1;
    }

    // ---- w_s extraction + zero col sidx ----
    const int fs = sidx >> 3, se = sidx & 1, hold = (sidx & 7) >> 1;
    float cand0 = 0.f, cand1 = 0.f;
#pragma unroll
    for (int f = 0; f < 10; f++) {
        if (f == fs) {
            cand0 = se ? c[f][1] : c[f][0];
            cand1 = se ? c[f][3] : c[f][2];
        }
    }
    const int src = (lane & ~3) | hold;
    const float ws0 = __shfl_sync(0xffffffffu, cand0, src);
    const float ws1 = __shfl_sync(0xffffffffu, cand1, src);
    if ((lane & 3) == hold) {
#pragma unroll
        for (int f = 0; f < 10; f++) {
            if (f == fs) { c[f][se] = 0.f; c[f][2 + se] = 0.f; }
        }
    }

    // ---- nested softmax (frag 10: cols 80-87, valid 80-83) ----
    {
        const bool nv = (lane & 3) < 2;
        const float n00 = nv ? c[10][0] : -1e30f;
        const float n01 = nv ? c[10][1] : -1e30f;
        const float n10 = nv ? c[10][2] : -1e30f;
        const float n11 = nv ? c[10][3] : -1e30f;
        float nm0 = fmaxf(n00, n01), nm1 = fmaxf(n10, n11);
        nm0 = fmaxf(nm0, __shfl_xor_sync(0xffffffffu, nm0, 1));
        nm0 = fmaxf(nm0, __shfl_xor_sync(0xffffffffu, nm0, 2));
        nm1 = fmaxf(nm1, __shfl_xor_sync(0xffffffffu, nm1, 1));
        nm1 = fmaxf(nm1, __shfl_xor_sync(0xffffffffu, nm1, 2));
        const float e00 = nv ? __expf(n00 - nm0) : 0.f;
        const float e01 = nv ? __expf(n01 - nm0) : 0.f;
        const float e10 = nv ? __expf(n10 - nm1) : 0.f;
        const float e11 = nv ? __expf(n11 - nm1) : 0.f;
        float ns0 = e00 + e01, ns1 = e10 + e11;
        ns0 += __shfl_xor_sync(0xffffffffu, ns0, 1);
        ns0 += __shfl_xor_sync(0xffffffffu, ns0, 2);
        ns1 += __shfl_xor_sync(0xffffffffu, ns1, 1);
        ns1 += __shfl_xor_sync(0xffffffffu, ns1, 2);
        const float sc0 = ws0 / ns0, sc1 = ws1 / ns1;
        c[10][0] = e00 * sc0; c[10][1] = e01 * sc0;
        c[10][2] = e10 * sc1; c[10][3] = e11 * sc1;
    }

    // ---- convert weights to A-fragments (FA2 identity) ----
    uint32_t aw[12][2];
#pragma unroll
    for (int f = 0; f < 11; f++) {
        const __half2 lo = __floats2half2_rn(c[f][0], c[f][1]);
        const __half2 hi = __floats2half2_rn(c[f][2], c[f][3]);
        aw[f][0] = *(const uint32_t*)&lo;
        aw[f][1] = *(const uint32_t*)&hi;
    }
    aw[11][0] = 0; aw[11][1] = 0;

    // ---- mma2: out = W' @ V' ----
    float o[8][4] = {};
#pragma unroll
    for (int g = 0; g < 6; g++) {
        const uint32_t A2[4] = { aw[2 * g][0], aw[2 * g][1], aw[2 * g + 1][0], aw[2 * g + 1][1] };
        uint32_t Bf[16];
#pragma unroll
        for (int t = 0; t < 4; t++)
            ldsm4t(&Bf[t * 4], vb + g * (16 * V_PITCH * 2) + t * 32);
#pragma unroll
        for (int f = 0; f < 8; f++) mma16816(o[f], A2, &Bf[f * 2]);
    }

    // ---- epilogue: fp16 store to g_attn ----
    const int r = lane >> 2;
    const size_t base0 = ((size_t)b * CHW + t0 + wtok + r) * CHID + (h0 + h) * 64;
    const size_t base1 = base0 + (size_t)8 * CHID;
#pragma unroll
    for (int f = 0; f < 8; f++) {
        const int dd = f * 8 + colb;
        *(__half2*)(g_attn + base0 + dd) = __floats2half2_rn(o[f][0], o[f][1]);
        *(__half2*)(g_attn + base1 + dd) = __floats2half2_rn(o[f][2], o[f][3]);
    }
}

// ---------------- launch ----------------
extern "C" void kernel_launch(void* const* d_in, const int* in_sizes, int n_in,
                              void* d_out, int out_size)
{
    (void)in_sizes; (void)n_in; (void)out_size;
    const float* hidden = (const float*)d_in[0];
    const float* enc    = (const float*)d_in[1];
    const int*   idx    = (const int*)  d_in[2];
    const float* Wq     = (const float*)d_in[3];
    const float* Wk     = (const float*)d_in[4];
    const float* Wv     = (const float*)d_in[5];
    const float* Wkn    = (const float*)d_in[6];
    const float* Wvn    = (const float*)d_in[7];
    const float* Wout   = (const float*)d_in[8];
    const float* bout   = (const float*)d_in[9];
    float* out = (float*)d_out;

    __half *hidp, *wqp, *wop, *atp, *encp, *wkp, *wvp, *wknp, *wvnp;
    float* qp;
    cudaGetSymbolAddress((void**)&hidp, g_hid);
    cudaGetSymbolAddress((void**)&wqp,  g_wq);
    cudaGetSymbolAddress((void**)&wop,  g_wo);
    cudaGetSymbolAddress((void**)&atp,  g_attn);
    cudaGetSymbolAddress((void**)&encp, g_enc);
    cudaGetSymbolAddress((void**)&wkp,  g_wk);
    cudaGetSymbolAddress((void**)&wvp,  g_wv);
    cudaGetSymbolAddress((void**)&wknp, g_wkn);
    cudaGetSymbolAddress((void**)&wvnp, g_wvn);
    cudaGetSymbolAddress((void**)&qp,   g_q);

    cudaFuncSetAttribute(gemm_f16, cudaFuncAttributeMaxDynamicSharedMemorySize, GEMM_SMEM);
    cudaFuncSetAttribute(proj_f16, cudaFuncAttributeMaxDynamicSharedMemorySize, PROJ_SMEM);
    cudaFuncSetAttribute(qattn_mma, cudaFuncAttributeMaxDynamicSharedMemorySize, (int)sizeof(SmQ));

    // 1) ALL conversions, one launch (8 segments)
    CvtArgs ca;
    ca.s[0] = { hidden, hidp, GM * GK };
    ca.s[1] = { Wq,   wqp,  GK * GN };
    ca.s[2] = { Wout, wop,  GK * GN };
    ca.s[3] = { Wk,   wkp,  CCAD * CHID };
    ca.s[4] = { Wv,   wvp,  CCAD * CHID };
    ca.s[5] = { Wkn,  wknp, CCAD * CHID };
    ca.s[6] = { Wvn,  wvnp, CCAD * CHID };
    ca.s[7] = { enc,  encp, CB * CENCL * CCAD };
    cvt_multi<<<dim3(160, 8), 512>>>(ca);

    // 2) K/V/KN/VN projections -> g_kv fp32
    proj_f16<<<dim3(CB, CHID / 128, 4), 512, PROJ_SMEM>>>();

    // 3) Q = hidden @ Wq
    gemm_f16<<<dim3(GM / 128, GN / 256), 512, GEMM_SMEM>>>(hidp, wqp, nullptr, qp);

    // 4) attention (tensor-core)
    qattn_mma<<<dim3(CB * 64, CNH / 2), 256, sizeof(SmQ)>>>(idx);

    // 5) out = attn @ Wout + bias
    gemm_f16<<<dim3(GM / 128, GN / 256), 512, GEMM_SMEM>>>(atp, wop, bout, out);
}

// round 16
// speedup vs baseline: 1.5464x; 1.1013x over previous
#include <cuda_runtime.h>
#include <cuda_fp16.h>
#include <cstdint>

#define CB    2
#define CHW   4096
#define CHID  1280
#define CCAD  2048
#define CLTXT 77
#define CNT   4
#define CNH   20
#define CENCL (CLTXT + CNT)

#define GM 8192
#define GK 1280
#define GN 1280

#define KT_PITCH 104   // halves per Kt row (64 rows/head), keys 0-76 txt, 80-83 nested
#define V_PITCH  72    // halves per V' row (96 rows/head), rows 77-79 & 84-95 zero

// ---------------- scratch (device globals; zero-initialized) ----------------
__device__ __half g_hid[(size_t)GM * GK];
__device__ __half g_wq[(size_t)GK * GN];
__device__ __half g_wo[(size_t)GK * GN];
__device__ __half g_attn[(size_t)GM * GK];
__device__ __half g_enc[(size_t)CB * CENCL * CCAD];
__device__ __half g_wk [(size_t)CCAD * CHID];
__device__ __half g_wv [(size_t)CCAD * CHID];
__device__ __half g_wkn[(size_t)CCAD * CHID];
__device__ __half g_wvn[(size_t)CCAD * CHID];
__device__ __half g_kth[(size_t)CB * CNH * 64 * KT_PITCH];   // K transposed, fp16, padded
__device__ __half g_kvh[(size_t)CB * CNH * 96 * V_PITCH];    // V' stacked,   fp16, padded

// =====================================================================
// fp32 -> fp16 converts: ALL segments in one launch
// =====================================================================
struct CvtSeg { const float* src; __half* dst; int len; };
struct CvtArgs { CvtSeg s[8]; };

__global__ __launch_bounds__(512) void cvt_multi(CvtArgs a)
{
    const CvtSeg seg = a.s[blockIdx.y];
    const float* __restrict__ x = seg.src;
    __half* __restrict__ y = seg.dst;
    for (int i = (blockIdx.x * 512 + threadIdx.x) * 4; i < seg.len; i += gridDim.x * 512 * 4) {
        const float4 v = *(const float4*)(x + i);
        *(__half2*)(y + i)     = __floats2half2_rn(v.x, v.y);
        *(__half2*)(y + i + 2) = __floats2half2_rn(v.z, v.w);
    }
}

// =====================================================================
// shared mma helpers
// =====================================================================
#define CP_ASYNC(dst, src) asm volatile("cp.async.cg.shared.global [%0], [%1], 16;" :: "r"(dst), "l"(src))
#define CP_ASYNC_Z(dst, src, ok) asm volatile("cp.async.cg.shared.global [%0], [%1], 16, %2;" :: "r"(dst), "l"(src), "r"((ok) ? 16 : 0))

__device__ __forceinline__ void ldsm4(uint32_t* r, uint32_t a) {
    asm volatile("ldmatrix.sync.aligned.m8n8.x4.shared.b16 {%0,%1,%2,%3}, [%4];"
        : "=r"(r[0]), "=r"(r[1]), "=r"(r[2]), "=r"(r[3]) : "r"(a));
}
__device__ __forceinline__ void ldsm4t(uint32_t* r, uint32_t a) {
    asm volatile("ldmatrix.sync.aligned.m8n8.x4.trans.shared.b16 {%0,%1,%2,%3}, [%4];"
        : "=r"(r[0]), "=r"(r[1]), "=r"(r[2]), "=r"(r[3]) : "r"(a));
}
__device__ __forceinline__ void mma16816(float* c, const uint32_t* a, const uint32_t* b) {
    asm volatile("mma.sync.aligned.m16n8k16.row.col.f32.f16.f16.f32 "
        "{%0,%1,%2,%3}, {%4,%5,%6,%7}, {%8,%9}, {%0,%1,%2,%3};"
        : "+f"(c[0]), "+f"(c[1]), "+f"(c[2]), "+f"(c[3])
        : "r"(a[0]), "r"(a[1]), "r"(a[2]), "r"(a[3]), "r"(b[0]), "r"(b[1]));
}

#define A_PITCH 40
#define ABUF (128 * A_PITCH)
#define NSTAGE 4
#define PB_PITCH 136
#define PBUF (32 * PB_PITCH)
#define PROJ_SMEM ((NSTAGE * ABUF + NSTAGE * PBUF) * 2)
#define GB_PITCH 264
#define GBUF (32 * GB_PITCH)
#define GEMM_SMEM ((NSTAGE * ABUF + NSTAGE * GBUF) * 2)

// fused kernel smem: [sA | sB | sKt | sV]
#define KT_HALVES (4 * 64 * KT_PITCH)    // 26624
#define V_HALVES  (4 * 96 * V_PITCH)     // 27648
#define FUSE_SMEM (GEMM_SMEM + (KT_HALVES + V_HALVES) * 2)   // 217088 B

// =====================================================================
// out-projection GEMM (v5): CTA 128x256, 512 thr / 16 warps, wt 32x64
// =====================================================================
__global__ __launch_bounds__(512, 1) void gemm_f16(
    const __half* __restrict__ A, const __half* __restrict__ B,
    const float* __restrict__ bias, float* __restrict__ C)
{
    extern __shared__ __align__(16) char sm[];
    __half* sA = (__half*)sm;
    __half* sB = sA + NSTAGE * ABUF;

    const int tid = threadIdx.x;
    const int m0 = blockIdx.x * 128, n0 = blockIdx.y * 256;
    const int lane = tid & 31, warp = tid >> 5;
    const int wm = warp & 3, wn = warp >> 2;

    const int arow = tid >> 2, ak8 = (tid & 3) << 3;
    const int brow = tid >> 5, bn8 = (tid & 31) << 3;
    const __half* gA = A + (size_t)(m0 + arow) * GK + ak8;
    const __half* gB = B + (size_t)brow * GN + n0 + bn8;
    const uint32_t dA = (uint32_t)__cvta_generic_to_shared(sA) + (uint32_t)(arow * A_PITCH + ak8) * 2;
    const uint32_t dB = (uint32_t)__cvta_generic_to_shared(sB) + (uint32_t)(brow * GB_PITCH + bn8) * 2;

#define LOADK5(stage, kt) do {                                                  \
        const uint32_t ao_ = (uint32_t)(stage) * (ABUF * 2);                    \
        const uint32_t bo_ = (uint32_t)(stage) * (GBUF * 2);                    \
        const size_t ka_ = (size_t)(kt) * 32;                                   \
        CP_ASYNC(dA + ao_, gA + ka_);                                           \
        CP_ASYNC(dB + bo_,                     gB + ka_ * GN);                  \
        CP_ASYNC(dB + bo_ + 16 * GB_PITCH * 2, gB + (ka_ + 16) * GN);           \
        asm volatile("cp.async.commit_group;");                                 \
    } while (0)

    LOADK5(0, 0);
    LOADK5(1, 1);
    LOADK5(2, 2);

    float acc[2][8][4] = {};

    const uint32_t aOff = (uint32_t)((wm * 32 + (lane & 15)) * A_PITCH + ((lane >> 4) << 3)) * 2;
    const uint32_t aB0 = (uint32_t)__cvta_generic_to_shared(sA) + aOff;
    const uint32_t bOff = (uint32_t)(((lane & 7) + ((lane >> 3) & 1) * 8) * GB_PITCH
                                     + wn * 64 + ((lane >> 4) << 3)) * 2;
    const uint32_t bB0 = (uint32_t)__cvta_generic_to_shared(sB) + bOff;

    const int NKT = GK / 32;   // 40
    for (int kt = 0; kt < NKT; kt++) {
        const int s = kt & (NSTAGE - 1);
        if (kt < NKT - 2)       asm volatile("cp.async.wait_group 2;");
        else if (kt == NKT - 2) asm volatile("cp.async.wait_group 1;");
        else                    asm volatile("cp.async.wait_group 0;");
        __syncthreads();

        const uint32_t ah = aB0 + s * (ABUF * 2);
        const uint32_t bh = bB0 + s * (GBUF * 2);
#pragma unroll
        for (int ks = 0; ks < 2; ks++) {
            const uint32_t ka = ah + ks * 32;
            const uint32_t kb = bh + ks * (16 * GB_PITCH * 2);
            uint32_t A0[4], A1[4];
            ldsm4(A0, ka);
            ldsm4(A1, ka + 16 * A_PITCH * 2);
            uint32_t Bf[16];
#pragma unroll
            for (int t = 0; t < 4; t++) ldsm4t(Bf + t * 4, kb + t * 32);
#pragma unroll
            for (int j = 0; j < 8; j++) {
                mma16816(acc[0][j], A0, &Bf[j * 2]);
                mma16816(acc[1][j], A1, &Bf[j * 2]);
            }
        }
        if (kt + 3 < NKT) {
            LOADK5((kt + 3) & (NSTAGE - 1), kt + 3);
        }
    }

#pragma unroll
    for (int f = 0; f < 2; f++) {
        const int r0 = m0 + wm * 32 + f * 16 + (lane >> 2);
#pragma unroll
        for (int j = 0; j < 8; j++) {
            const int cc = n0 + wn * 64 + j * 8 + ((lane & 3) << 1);
            float b0 = 0.f, b1 = 0.f;
            if (bias) { b0 = bias[cc]; b1 = bias[cc + 1]; }
            *(float2*)(C + (size_t)r0 * GN + cc) =
                make_float2(acc[f][j][0] + b0, acc[f][j][1] + b1);
            *(float2*)(C + (size_t)(r0 + 8) * GN + cc) =
                make_float2(acc[f][j][2] + b0, acc[f][j][3] + b1);
        }
    }
#undef LOADK5
}

// =====================================================================
// fp16 projection GEMM, masked M; writes attention-ready fp16 layouts:
//   K/KN -> g_kth [b][h][dim 64][KT_PITCH]  (transposed, keys 0-76, 80-83)
//   V/VN -> g_kvh [b][h][key 96][V_PITCH]   (rows 0-76, 80-83)
// =====================================================================
__global__ __launch_bounds__(512, 1) void proj_f16()
{
    extern __shared__ __align__(16) char sm[];
    __half* sA = (__half*)sm;
    __half* sB = sA + NSTAGE * ABUF;

    const int tid = threadIdx.x;
    const int b = blockIdx.x, n0 = blockIdx.y * 128, type = blockIdx.z;
    const int M = (type < 2) ? CLTXT : CNT;
    const __half* Asrc = g_enc + (size_t)b * CENCL * CCAD + ((type >= 2) ? (size_t)CLTXT * CCAD : 0);
    const __half* Bsrc = (type == 0) ? g_wk : (type == 1) ? g_wv : (type == 2) ? g_wkn : g_wvn;

    const int lane = tid & 31, warp = tid >> 5;
    const int wm = warp >> 2, wn = warp & 3;

    const int arow = tid >> 2, ak8 = (tid & 3) << 3;
    const int brow = tid >> 4, bn8 = (tid & 15) << 3;
    const bool aok = arow < M;
    const __half* gA = Asrc + (size_t)arow * CCAD + ak8;
    const __half* gB = Bsrc + (size_t)brow * CHID + n0 + bn8;
    const uint32_t dA = (uint32_t)__cvta_generic_to_shared(sA) + (uint32_t)(arow * A_PITCH + ak8) * 2;
    const uint32_t dB = (uint32_t)__cvta_generic_to_shared(sB) + (uint32_t)(brow * PB_PITCH + bn8) * 2;

#define LOADKP(stage, kt) do {                                                  \
        const uint32_t ao_ = (uint32_t)(stage) * (ABUF * 2);                    \
        const uint32_t bo_ = (uint32_t)(stage) * (PBUF * 2);                    \
        const size_t kofs_ = (size_t)(kt) * 32;                                 \
        CP_ASYNC_Z(dA + ao_, gA + kofs_, aok);                                  \
        CP_ASYNC(dB + bo_, gB + kofs_ * CHID);                                  \
        asm volatile("cp.async.commit_group;");                                 \
    } while (0)

    LOADKP(0, 0);
    LOADKP(1, 1);
    LOADKP(2, 2);

    float acc[2][4][4] = {};

    const uint32_t aOff = (uint32_t)((wm * 32 + (lane & 15)) * A_PITCH + ((lane >> 4) << 3)) * 2;
    const uint32_t aB0 = (uint32_t)__cvta_generic_to_shared(sA) + aOff;
    const uint32_t bOff = (uint32_t)(((lane & 7) + ((lane >> 3) & 1) * 8) * PB_PITCH
                                     + wn * 32 + ((lane >> 4) << 3)) * 2;
    const uint32_t bB0 = (uint32_t)__cvta_generic_to_shared(sB) + bOff;

    const int NKT = CCAD / 32;   // 64
    for (int kt = 0; kt < NKT; kt++) {
        const int s = kt & (NSTAGE - 1);
        if (kt < NKT - 2)       asm volatile("cp.async.wait_group 2;");
        else if (kt == NKT - 2) asm volatile("cp.async.wait_group 1;");
        else                    asm volatile("cp.async.wait_group 0;");
        __syncthreads();

        const uint32_t ah = aB0 + s * (ABUF * 2);
        const uint32_t bh = bB0 + s * (PBUF * 2);
#pragma unroll
        for (int ks = 0; ks < 2; ks++) {
            const uint32_t ka = ah + ks * 32;
            const uint32_t kb = bh + ks * (16 * PB_PITCH * 2);
            uint32_t A0[4], A1[4];
            ldsm4(A0, ka);
            ldsm4(A1, ka + 16 * A_PITCH * 2);
            uint32_t Bf[8];
            ldsm4t(Bf,     kb);
            ldsm4t(Bf + 4, kb + 32);
#pragma unroll
            for (int j = 0; j < 4; j++) {
                mma16816(acc[0][j], A0, &Bf[j * 2]);
                mma16816(acc[1][j], A1, &Bf[j * 2]);
            }
        }
        if (kt + 3 < NKT) {
            LOADKP((kt + 3) & (NSTAGE - 1), kt + 3);
        }
    }

    // epilogue: scatter fp16 into attention-ready layouts
    const int colb = (lane & 3) << 1;
    const int keyofs = (type >= 2) ? 80 : 0;
#pragma unroll
    for (int fm = 0; fm < 2; fm++) {
        const int r = wm * 32 + fm * 16 + (lane >> 2);
#pragma unroll
        for (int rr = 0; rr < 2; rr++) {
            const int row = r + rr * 8;              // key index within type
            if (row >= M) continue;
            const int key = keyofs + row;
#pragma unroll
            for (int j = 0; j < 4; j++) {
                const int cc = n0 + wn * 32 + j * 8 + colb;   // global 0..1279
                const int h = cc >> 6, d = cc & 63;
                const float v0 = acc[fm][j][rr * 2 + 0];
                const float v1 = acc[fm][j][rr * 2 + 1];
                if ((type & 1) == 0) {   // K / KN -> transposed
                    __half* p = g_kth + ((size_t)(b * CNH + h) * 64) * KT_PITCH;
                    p[(size_t)d * KT_PITCH + key]       = __float2half(v0);
                    p[(size_t)(d + 1) * KT_PITCH + key] = __float2half(v1);
                } else {                 // V / VN -> row-major stacked
                    __half* p = g_kvh + ((size_t)(b * CNH + h) * 96 + key) * V_PITCH;
                    *(__half2*)(p + d) = __floats2half2_rn(v0, v1);
                }
            }
        }
    }
#undef LOADKP
}

// =====================================================================
// FUSED Q-GEMM + attention. 256 thr / 8 warps (wm 2 x wn 4),
// warp tile 64 tok x 64 cols = one full head. n-tile 256 = 4 heads.
// Kt/V' streamed via an extra cp.async group under the GEMM mainloop.
// =====================================================================
__global__ __launch_bounds__(256) void qgemm_attn(const int* __restrict__ idx_alter)
{
    extern __shared__ __align__(16) char sm[];
    __half* sA  = (__half*)sm;
    __half* sB  = sA + NSTAGE * ABUF;
    __half* sKt = sB + NSTAGE * GBUF;
    __half* sV  = sKt + KT_HALVES;

    const int tid = threadIdx.x;
    const int m0 = blockIdx.x * 128, n0 = blockIdx.y * 256;
    const int b = blockIdx.x >> 5;            // 32 m-tiles per batch
    const int hgbase = n0 >> 6;               // first of 4 heads
    const int lane = tid & 31, warp = tid >> 5;
    const int wm = warp & 1, wn = warp >> 1;  // 2 x 4 warps

    // ---- KV staging: ONE cp.async group, committed FIRST ----
    {
        const uint32_t dkt = (uint32_t)__cvta_generic_to_shared(sKt);
        const uint32_t dv  = (uint32_t)__cvta_generic_to_shared(sV);
        const __half* skt = g_kth + (size_t)(b * CNH + hgbase) * 64 * KT_PITCH;
        const __half* sv  = g_kvh + (size_t)(b * CNH + hgbase) * 96 * V_PITCH;
#pragma unroll
        for (int c = 0; c < KT_HALVES / 8; c += 256) {
            const int i = c + tid;
            if (i < KT_HALVES / 8) CP_ASYNC(dkt + i * 16, skt + (size_t)i * 8);
        }
#pragma unroll
        for (int c = 0; c < V_HALVES / 8; c += 256) {
            const int i = c + tid;
            if (i < V_HALVES / 8) CP_ASYNC(dv + i * 16, sv + (size_t)i * 8);
        }
        asm volatile("cp.async.commit_group;");
    }

    // ---- GEMM staging setup (v4: 256 threads) ----
    const int arow = tid >> 2, ak8 = (tid & 3) << 3;
    const int brow = tid >> 5, bn8 = (tid & 31) << 3;
    const __half* gA = g_hid + (size_t)(m0 + arow) * GK + ak8;
    const __half* gB = g_wq + (size_t)brow * GN + n0 + bn8;
    const uint32_t dA = (uint32_t)__cvta_generic_to_shared(sA) + (uint32_t)(arow * A_PITCH + ak8) * 2;
    const uint32_t dB = (uint32_t)__cvta_generic_to_shared(sB) + (uint32_t)(brow * GB_PITCH + bn8) * 2;

#define LOADK4(stage, kt) do {                                                  \
        const uint32_t ao_ = (uint32_t)(stage) * (ABUF * 2);                    \
        const uint32_t bo_ = (uint32_t)(stage) * (GBUF * 2);                    \
        const size_t ka_ = (size_t)(kt) * 32;                                   \
        CP_ASYNC(dA + ao_, gA + ka_);                                           \
        CP_ASYNC(dA + ao_ + 64 * A_PITCH * 2, gA + (size_t)64 * GK + ka_);      \
        CP_ASYNC(dB + bo_,                     gB + ka_ * GN);                  \
        CP_ASYNC(dB + bo_ +  8 * GB_PITCH * 2, gB + (ka_ +  8) * GN);           \
        CP_ASYNC(dB + bo_ + 16 * GB_PITCH * 2, gB + (ka_ + 16) * GN);           \
        CP_ASYNC(dB + bo_ + 24 * GB_PITCH * 2, gB + (ka_ + 24) * GN);           \
        asm volatile("cp.async.commit_group;");                                 \
    } while (0)

    LOADK4(0, 0);
    LOADK4(1, 1);
    LOADK4(2, 2);

    float acc[4][8][4] = {};

    const uint32_t aOff = (uint32_t)((wm * 64 + (lane & 15)) * A_PITCH + ((lane >> 4) << 3)) * 2;
    const uint32_t aB0 = (uint32_t)__cvta_generic_to_shared(sA) + aOff;
    const uint32_t bOff = (uint32_t)(((lane & 7) + ((lane >> 3) & 1) * 8) * GB_PITCH
                                     + wn * 64 + ((lane >> 4) << 3)) * 2;
    const uint32_t bB0 = (uint32_t)__cvta_generic_to_shared(sB) + bOff;

    const int NKT = GK / 32;   // 40
    for (int kt = 0; kt < NKT; kt++) {
        const int s = kt & (NSTAGE - 1);
        // FIFO completion: KV group is oldest, completes before k0.
        if (kt < NKT - 2)       asm volatile("cp.async.wait_group 2;");
        else if (kt == NKT - 2) asm volatile("cp.async.wait_group 1;");
        else                    asm volatile("cp.async.wait_group 0;");
        __syncthreads();

        const uint32_t ah = aB0 + s * (ABUF * 2);
        const uint32_t bh = bB0 + s * (GBUF * 2);
#pragma unroll
        for (int ks = 0; ks < 2; ks++) {
            const uint32_t ka = ah + ks * 32;
            const uint32_t kb = bh + ks * (16 * GB_PITCH * 2);
            uint32_t Af[4][4];
#pragma unroll
            for (int f = 0; f < 4; f++) ldsm4(Af[f], ka + f * (16 * A_PITCH * 2));
            uint32_t Bf[16];
#pragma unroll
            for (int t = 0; t < 4; t++) ldsm4t(Bf + t * 4, kb + t * 32);
#pragma unroll
            for (int f = 0; f < 4; f++)
#pragma unroll
                for (int j = 0; j < 8; j++)
                    mma16816(acc[f][j], Af[f], &Bf[j * 2]);
        }
        if (kt + 3 < NKT) {
            LOADK4((kt + 3) & (NSTAGE - 1), kt + 3);
        }
    }
    __syncthreads();

    // ---- convert Q accumulators to fp16 A-fragments (scale 1/8 folded) ----
    uint32_t qa[4][16];
#pragma unroll
    for (int f = 0; f < 4; f++)
#pragma unroll
        for (int kc = 0; kc < 4; kc++) {
            const __half2 a0 = __floats2half2_rn(acc[f][2 * kc][0] * 0.125f, acc[f][2 * kc][1] * 0.125f);
            const __half2 a1 = __floats2half2_rn(acc[f][2 * kc][2] * 0.125f, acc[f][2 * kc][3] * 0.125f);
            const __half2 a2 = __floats2half2_rn(acc[f][2 * kc + 1][0] * 0.125f, acc[f][2 * kc + 1][1] * 0.125f);
            const __half2 a3 = __floats2half2_rn(acc[f][2 * kc + 1][2] * 0.125f, acc[f][2 * kc + 1][3] * 0.125f);
            qa[f][kc * 4 + 0] = *(const uint32_t*)&a0;
            qa[f][kc * 4 + 1] = *(const uint32_t*)&a1;
            qa[f][kc * 4 + 2] = *(const uint32_t*)&a2;
            qa[f][kc * 4 + 3] = *(const uint32_t*)&a3;
        }

    const int sidx = idx_alter[b];
    const int h = wn;   // head within the 4-head tile
    const uint32_t ktb = (uint32_t)__cvta_generic_to_shared(sKt) + (uint32_t)h * 64 * KT_PITCH * 2
        + (uint32_t)(((lane & 7) + ((lane >> 3) & 1) * 8) * KT_PITCH + ((lane >> 4) << 3)) * 2;
    const uint32_t vb = (uint32_t)__cvta_generic_to_shared(sV) + (uint32_t)h * 96 * V_PITCH * 2
        + (uint32_t)(((lane & 7) + ((lane >> 3) & 1) * 8) * V_PITCH + ((lane >> 4) << 3)) * 2;
    const int colb = (lane & 3) << 1;
    const int r = lane >> 2;

    // ---- per 16-token group: mma1 -> softmax -> fold -> mma2 -> store ----
#pragma unroll
    for (int f = 0; f < 4; f++) {
        float c[11][4] = {};
#pragma unroll
        for (int kc = 0; kc < 4; kc++) {
            uint32_t Bf[24];
#pragma unroll
            for (int t = 0; t < 6; t++)
                ldsm4t(&Bf[t * 4], ktb + kc * (16 * KT_PITCH * 2) + t * 32);
#pragma unroll
            for (int ff = 0; ff < 11; ff++) mma16816(c[ff], &qa[f][kc * 4], &Bf[ff * 2]);
        }

        // txt softmax (cols 0-76)
        float m0v = -1e30f, m1v = -1e30f;
#pragma unroll
        for (int ff = 0; ff < 10; ff++) {
            const int col = ff * 8 + colb;
            if (col < CLTXT)     { m0v = fmaxf(m0v, c[ff][0]); m1v = fmaxf(m1v, c[ff][2]); }
            if (col + 1 < CLTXT) { m0v = fmaxf(m0v, c[ff][1]); m1v = fmaxf(m1v, c[ff][3]); }
        }
        m0v = fmaxf(m0v, __shfl_xor_sync(0xffffffffu, m0v, 1));
        m0v = fmaxf(m0v, __shfl_xor_sync(0xffffffffu, m0v, 2));
        m1v = fmaxf(m1v, __shfl_xor_sync(0xffffffffu, m1v, 1));
        m1v = fmaxf(m1v, __shfl_xor_sync(0xffffffffu, m1v, 2));
        float s0 = 0.f, s1 = 0.f;
#pragma unroll
        for (int ff = 0; ff < 10; ff++) {
            const int col = ff * 8 + colb;
            c[ff][0] = (col < CLTXT)     ? __expf(c[ff][0] - m0v) : 0.f;
            c[ff][1] = (col + 1 < CLTXT) ? __expf(c[ff][1] - m0v) : 0.f;
            c[ff][2] = (col < CLTXT)     ? __expf(c[ff][2] - m1v) : 0.f;
            c[ff][3] = (col + 1 < CLTXT) ? __expf(c[ff][3] - m1v) : 0.f;
            s0 += c[ff][0] + c[ff][1];
            s1 += c[ff][2] + c[ff][3];
        }
        s0 += __shfl_xor_sync(0xffffffffu, s0, 1);
        s0 += __shfl_xor_sync(0xffffffffu, s0, 2);
        s1 += __shfl_xor_sync(0xffffffffu, s1, 1);
        s1 += __shfl_xor_sync(0xffffffffu, s1, 2);
        const float inv0 = 1.f / s0, inv1 = 1.f / s1;
#pragma unroll
        for (int ff = 0; ff < 10; ff++) {
            c[ff][0] *= inv0; c[ff][1] *= inv0;
            c[ff][2] *= inv1; c[ff][3] *= inv1;
        }

        // w_s extraction + zero col sidx
        const int fs = sidx >> 3, se = sidx & 1, hold = (sidx & 7) >> 1;
        float cand0 = 0.f, cand1 = 0.f;
#pragma unroll
        for (int ff = 0; ff < 10; ff++) {
            if (ff == fs) {
                cand0 = se ? c[ff][1] : c[ff][0];
                cand1 = se ? c[ff][3] : c[ff][2];
            }
        }
        const int src = (lane & ~3) | hold;
        const float ws0 = __shfl_sync(0xffffffffu, cand0, src);
        const float ws1 = __shfl_sync(0xffffffffu, cand1, src);
        if ((lane & 3) == hold) {
#pragma unroll
            for (int ff = 0; ff < 10; ff++) {
                if (ff == fs) { c[ff][se] = 0.f; c[ff][2 + se] = 0.f; }
            }
        }

        // nested softmax (frag 10, cols 80-83) scaled by w_s
        {
            const bool nv = (lane & 3) < 2;
            const float n00 = nv ? c[10][0] : -1e30f;
            const float n01 = nv ? c[10][1] : -1e30f;
            const float n10 = nv ? c[10][2] : -1e30f;
            const float n11 = nv ? c[10][3] : -1e30f;
            float nm0 = fmaxf(n00, n01), nm1 = fmaxf(n10, n11);
            nm0 = fmaxf(nm0, __shfl_xor_sync(0xffffffffu, nm0, 1));
            nm0 = fmaxf(nm0, __shfl_xor_sync(0xffffffffu, nm0, 2));
            nm1 = fmaxf(nm1, __shfl_xor_sync(0xffffffffu, nm1, 1));
            nm1 = fmaxf(nm1, __shfl_xor_sync(0xffffffffu, nm1, 2));
            const float e00 = nv ? __expf(n00 - nm0) : 0.f;
            const float e01 = nv ? __expf(n01 - nm0) : 0.f;
            const float e10 = nv ? __expf(n10 - nm1) : 0.f;
            const float e11 = nv ? __expf(n11 - nm1) : 0.f;
            float ns0 = e00 + e01, ns1 = e10 + e11;
            ns0 += __shfl_xor_sync(0xffffffffu, ns0, 1);
            ns0 += __shfl_xor_sync(0xffffffffu, ns0, 2);
            ns1 += __shfl_xor_sync(0xffffffffu, ns1, 1);
            ns1 += __shfl_xor_sync(0xffffffffu, ns1, 2);
            const float sc0 = ws0 / ns0, sc1 = ws1 / ns1;
            c[10][0] = e00 * sc0; c[10][1] = e01 * sc0;
            c[10][2] = e10 * sc1; c[10][3] = e11 * sc1;
        }

        // weights -> A fragments
        uint32_t aw[12][2];
#pragma unroll
        for (int ff = 0; ff < 11; ff++) {
            const __half2 lo = __floats2half2_rn(c[ff][0], c[ff][1]);
            const __half2 hi = __floats2half2_rn(c[ff][2], c[ff][3]);
            aw[ff][0] = *(const uint32_t*)&lo;
            aw[ff][1] = *(const uint32_t*)&hi;
        }
        aw[11][0] = 0; aw[11][1] = 0;

        // mma2: out = W' @ V'
        float o[8][4] = {};
#pragma unroll
        for (int g = 0; g < 6; g++) {
            const uint32_t A2[4] = { aw[2 * g][0], aw[2 * g][1], aw[2 * g + 1][0], aw[2 * g + 1][1] };
            uint32_t Bf[16];
#pragma unroll
            for (int t = 0; t < 4; t++)
                ldsm4t(&Bf[t * 4], vb + g * (16 * V_PITCH * 2) + t * 32);
#pragma unroll
            for (int ff = 0; ff < 8; ff++) mma16816(o[ff], A2, &Bf[ff * 2]);
        }

        // store fp16 to g_attn
        const size_t tok0 = (size_t)(m0 + wm * 64 + f * 16 + r);
        const size_t base0 = tok0 * CHID + n0 + wn * 64;
        const size_t base1 = base0 + (size_t)8 * CHID;
#pragma unroll
        for (int ff = 0; ff < 8; ff++) {
            const int dd = ff * 8 + colb;
            *(__half2*)(g_attn + base0 + dd) = __floats2half2_rn(o[ff][0], o[ff][1]);
            *(__half2*)(g_attn + base1 + dd) = __floats2half2_rn(o[ff][2], o[ff][3]);
        }
    }
#undef LOADK4
}

// ---------------- launch ----------------
extern "C" void kernel_launch(void* const* d_in, const int* in_sizes, int n_in,
                              void* d_out, int out_size)
{
    (void)in_sizes; (void)n_in; (void)out_size;
    const float* hidden = (const float*)d_in[0];
    const float* enc    = (const float*)d_in[1];
    const int*   idx    = (const int*)  d_in[2];
    const float* Wq     = (const float*)d_in[3];
    const float* Wk     = (const float*)d_in[4];
    const float* Wv     = (const float*)d_in[5];
    const float* Wkn    = (const float*)d_in[6];
    const float* Wvn    = (const float*)d_in[7];
    const float* Wout   = (const float*)d_in[8];
    const float* bout   = (const float*)d_in[9];
    float* out = (float*)d_out;

    __half *hidp, *wqp, *wop, *atp, *encp, *wkp, *wvp, *wknp, *wvnp;
    cudaGetSymbolAddress((void**)&hidp, g_hid);
    cudaGetSymbolAddress((void**)&wqp,  g_wq);
    cudaGetSymbolAddress((void**)&wop,  g_wo);
    cudaGetSymbolAddress((void**)&atp,  g_attn);
    cudaGetSymbolAddress((void**)&encp, g_enc);
    cudaGetSymbolAddress((void**)&wkp,  g_wk);
    cudaGetSymbolAddress((void**)&wvp,  g_wv);
    cudaGetSymbolAddress((void**)&wknp, g_wkn);
    cudaGetSymbolAddress((void**)&wvnp, g_wvn);

    cudaFuncSetAttribute(gemm_f16, cudaFuncAttributeMaxDynamicSharedMemorySize, GEMM_SMEM);
    cudaFuncSetAttribute(proj_f16, cudaFuncAttributeMaxDynamicSharedMemorySize, PROJ_SMEM);
    cudaFuncSetAttribute(qgemm_attn, cudaFuncAttributeMaxDynamicSharedMemorySize, FUSE_SMEM);

    // 1) ALL conversions, one launch (8 segments)
    CvtArgs ca;
    ca.s[0] = { hidden, hidp, GM * GK };
    ca.s[1] = { Wq,   wqp,  GK * GN };
    ca.s[2] = { Wout, wop,  GK * GN };
    ca.s[3] = { Wk,   wkp,  CCAD * CHID };
    ca.s[4] = { Wv,   wvp,  CCAD * CHID };
    ca.s[5] = { Wkn,  wknp, CCAD * CHID };
    ca.s[6] = { Wvn,  wvnp, CCAD * CHID };
    ca.s[7] = { enc,  encp, CB * CENCL * CCAD };
    cvt_multi<<<dim3(160, 8), 512>>>(ca);

    // 2) K/V/KN/VN projections -> attention-ready fp16 layouts
    proj_f16<<<dim3(CB, CHID / 128, 4), 512, PROJ_SMEM>>>();

    // 3) FUSED: Q = hidden @ Wq  + attention  -> g_attn fp16
    qgemm_attn<<<dim3(GM / 128, GN / 256), 256, FUSE_SMEM>>>(idx);

    // 4) out = attn @ Wout + bias
    gemm_f16<<<dim3(GM / 128, GN / 256), 512, GEMM_SMEM>>>(atp, wop, bout, out);
}

// round 17
// speedup vs baseline: 1.8592x; 1.2023x over previous
#include <cuda_runtime.h>
#include <cuda_fp16.h>
#include <cstdint>

#define CB    2
#define CHW   4096
#define CHID  1280
#define CCAD  2048
#define CLTXT 77
#define CNT   4
#define CNH   20
#define CENCL (CLTXT + CNT)

#define GM 8192
#define GK 1280
#define GN 1280

#define KT_PITCH 104   // halves per Kt row (64 rows/head)
#define V_PITCH  72    // halves per V' row (96 rows/head)

// ---------------- scratch (device globals; zero-initialized) ----------------
__device__ __half g_hid[(size_t)GM * GK];
__device__ __half g_wq[(size_t)GK * GN];
__device__ __half g_wo[(size_t)GK * GN];
__device__ __half g_attn[(size_t)GM * GK];
__device__ __half g_enc[(size_t)CB * CENCL * CCAD];
__device__ __half g_wk [(size_t)CCAD * CHID];
__device__ __half g_wv [(size_t)CCAD * CHID];
__device__ __half g_wkn[(size_t)CCAD * CHID];
__device__ __half g_wvn[(size_t)CCAD * CHID];
__device__ __half g_kth[(size_t)CB * CNH * 64 * KT_PITCH];
__device__ __half g_kvh[(size_t)CB * CNH * 96 * V_PITCH];

// =====================================================================
// fp32 -> fp16 converts: ALL segments in one launch
// =====================================================================
struct CvtSeg { const float* src; __half* dst; int len; };
struct CvtArgs { CvtSeg s[8]; };

__global__ __launch_bounds__(512) void cvt_multi(CvtArgs a)
{
    const CvtSeg seg = a.s[blockIdx.y];
    const float* __restrict__ x = seg.src;
    __half* __restrict__ y = seg.dst;
    for (int i = (blockIdx.x * 512 + threadIdx.x) * 4; i < seg.len; i += gridDim.x * 512 * 4) {
        const float4 v = *(const float4*)(x + i);
        *(__half2*)(y + i)     = __floats2half2_rn(v.x, v.y);
        *(__half2*)(y + i + 2) = __floats2half2_rn(v.z, v.w);
    }
}

// =====================================================================
// shared mma helpers
// =====================================================================
#define CP_ASYNC(dst, src) asm volatile("cp.async.cg.shared.global [%0], [%1], 16;" :: "r"(dst), "l"(src))
#define CP_ASYNC_Z(dst, src, ok) asm volatile("cp.async.cg.shared.global [%0], [%1], 16, %2;" :: "r"(dst), "l"(src), "r"((ok) ? 16 : 0))

__device__ __forceinline__ void ldsm4(uint32_t* r, uint32_t a) {
    asm volatile("ldmatrix.sync.aligned.m8n8.x4.shared.b16 {%0,%1,%2,%3}, [%4];"
        : "=r"(r[0]), "=r"(r[1]), "=r"(r[2]), "=r"(r[3]) : "r"(a));
}
__device__ __forceinline__ void ldsm4t(uint32_t* r, uint32_t a) {
    asm volatile("ldmatrix.sync.aligned.m8n8.x4.trans.shared.b16 {%0,%1,%2,%3}, [%4];"
        : "=r"(r[0]), "=r"(r[1]), "=r"(r[2]), "=r"(r[3]) : "r"(a));
}
__device__ __forceinline__ void mma16816(float* c, const uint32_t* a, const uint32_t* b) {
    asm volatile("mma.sync.aligned.m16n8k16.row.col.f32.f16.f16.f32 "
        "{%0,%1,%2,%3}, {%4,%5,%6,%7}, {%8,%9}, {%0,%1,%2,%3};"
        : "+f"(c[0]), "+f"(c[1]), "+f"(c[2]), "+f"(c[3])
        : "r"(a[0]), "r"(a[1]), "r"(a[2]), "r"(a[3]), "r"(b[0]), "r"(b[1]));
}

#define A_PITCH 40
#define ABUF (128 * A_PITCH)
#define PB_PITCH 136
#define PBUF (32 * PB_PITCH)
#define PROJ_SMEM ((4 * ABUF + 4 * PBUF) * 2)          // 4-stage, 128x128

// out-proj v6: 128x128, 4-stage
#define GEMM_SMEM ((4 * ABUF + 4 * PBUF) * 2)          // 75776 B

// fused v2: 128x128 GEMM (3-stage) + 2-head KV
#define KT2_HALVES (2 * 64 * KT_PITCH)    // 13312
#define V2_HALVES  (2 * 96 * V_PITCH)     // 13824
#define FUSE_SMEM ((3 * ABUF + 3 * PBUF) * 2 + (KT2_HALVES + V2_HALVES) * 2)  // 111104 B

// =====================================================================
// out-projection GEMM v6: CTA 128x128, 256 thr / 8 warps (4x2), wt 32x64,
// 4-stage, 2 CTAs/SM
// =====================================================================
__global__ __launch_bounds__(256, 2) void gemm_f16(
    const __half* __restrict__ A, const __half* __restrict__ B,
    const float* __restrict__ bias, float* __restrict__ C)
{
    extern __shared__ __align__(16) char sm[];
    __half* sA = (__half*)sm;
    __half* sB = sA + 4 * ABUF;

    const int tid = threadIdx.x;
    const int m0 = blockIdx.x * 128, n0 = blockIdx.y * 128;
    const int lane = tid & 31, warp = tid >> 5;
    const int wm = warp & 3, wn = warp >> 2;

    const int arow = tid >> 2, ak8 = (tid & 3) << 3;
    const int brow = tid >> 4, bn8 = (tid & 15) << 3;
    const __half* gA = A + (size_t)(m0 + arow) * GK + ak8;
    const __half* gB = B + (size_t)brow * GN + n0 + bn8;
    const uint32_t dA = (uint32_t)__cvta_generic_to_shared(sA) + (uint32_t)(arow * A_PITCH + ak8) * 2;
    const uint32_t dB = (uint32_t)__cvta_generic_to_shared(sB) + (uint32_t)(brow * PB_PITCH + bn8) * 2;

#define LOADK6(stage, kt) do {                                                  \
        const uint32_t ao_ = (uint32_t)(stage) * (ABUF * 2);                    \
        const uint32_t bo_ = (uint32_t)(stage) * (PBUF * 2);                    \
        const size_t ka_ = (size_t)(kt) * 32;                                   \
        CP_ASYNC(dA + ao_, gA + ka_);                                           \
        CP_ASYNC(dA + ao_ + 64 * A_PITCH * 2, gA + (size_t)64 * GK + ka_);      \
        CP_ASYNC(dB + bo_,                     gB + ka_ * GN);                  \
        CP_ASYNC(dB + bo_ + 16 * PB_PITCH * 2, gB + (ka_ + 16) * GN);           \
        asm volatile("cp.async.commit_group;");                                 \
    } while (0)

    LOADK6(0, 0);
    LOADK6(1, 1);
    LOADK6(2, 2);

    float acc[2][8][4] = {};

    const uint32_t aOff = (uint32_t)((wm * 32 + (lane & 15)) * A_PITCH + ((lane >> 4) << 3)) * 2;
    const uint32_t aB0 = (uint32_t)__cvta_generic_to_shared(sA) + aOff;
    const uint32_t bOff = (uint32_t)(((lane & 7) + ((lane >> 3) & 1) * 8) * PB_PITCH
                                     + wn * 64 + ((lane >> 4) << 3)) * 2;
    const uint32_t bB0 = (uint32_t)__cvta_generic_to_shared(sB) + bOff;

    const int NKT = GK / 32;   // 40
    for (int kt = 0; kt < NKT; kt++) {
        const int s = kt & 3;
        if (kt < NKT - 2)       asm volatile("cp.async.wait_group 2;");
        else if (kt == NKT - 2) asm volatile("cp.async.wait_group 1;");
        else                    asm volatile("cp.async.wait_group 0;");
        __syncthreads();

        const uint32_t ah = aB0 + s * (ABUF * 2);
        const uint32_t bh = bB0 + s * (PBUF * 2);
#pragma unroll
        for (int ks = 0; ks < 2; ks++) {
            const uint32_t ka = ah + ks * 32;
            const uint32_t kb = bh + ks * (16 * PB_PITCH * 2);
            uint32_t A0[4], A1[4];
            ldsm4(A0, ka);
            ldsm4(A1, ka + 16 * A_PITCH * 2);
            uint32_t Bf[16];
#pragma unroll
            for (int t = 0; t < 4; t++) ldsm4t(Bf + t * 4, kb + t * 32);
#pragma unroll
            for (int j = 0; j < 8; j++) {
                mma16816(acc[0][j], A0, &Bf[j * 2]);
                mma16816(acc[1][j], A1, &Bf[j * 2]);
            }
        }
        if (kt + 3 < NKT) {
            LOADK6((kt + 3) & 3, kt + 3);
        }
    }

#pragma unroll
    for (int f = 0; f < 2; f++) {
        const int r0 = m0 + wm * 32 + f * 16 + (lane >> 2);
#pragma unroll
        for (int j = 0; j < 8; j++) {
            const int cc = n0 + wn * 64 + j * 8 + ((lane & 3) << 1);
            float b0 = 0.f, b1 = 0.f;
            if (bias) { b0 = bias[cc]; b1 = bias[cc + 1]; }
            *(float2*)(C + (size_t)r0 * GN + cc) =
                make_float2(acc[f][j][0] + b0, acc[f][j][1] + b1);
            *(float2*)(C + (size_t)(r0 + 8) * GN + cc) =
                make_float2(acc[f][j][2] + b0, acc[f][j][3] + b1);
        }
    }
#undef LOADK6
}

// =====================================================================
// fp16 projection GEMM, masked M; writes attention-ready fp16 layouts
// =====================================================================
__global__ __launch_bounds__(512, 1) void proj_f16()
{
    extern __shared__ __align__(16) char sm[];
    __half* sA = (__half*)sm;
    __half* sB = sA + 4 * ABUF;

    const int tid = threadIdx.x;
    const int b = blockIdx.x, n0 = blockIdx.y * 128, type = blockIdx.z;
    const int M = (type < 2) ? CLTXT : CNT;
    const __half* Asrc = g_enc + (size_t)b * CENCL * CCAD + ((type >= 2) ? (size_t)CLTXT * CCAD : 0);
    const __half* Bsrc = (type == 0) ? g_wk : (type == 1) ? g_wv : (type == 2) ? g_wkn : g_wvn;

    const int lane = tid & 31, warp = tid >> 5;
    const int wm = warp >> 2, wn = warp & 3;

    const int arow = tid >> 2, ak8 = (tid & 3) << 3;
    const int brow = tid >> 4, bn8 = (tid & 15) << 3;
    const bool aok = arow < M;
    const __half* gA = Asrc + (size_t)arow * CCAD + ak8;
    const __half* gB = Bsrc + (size_t)brow * CHID + n0 + bn8;
    const uint32_t dA = (uint32_t)__cvta_generic_to_shared(sA) + (uint32_t)(arow * A_PITCH + ak8) * 2;
    const uint32_t dB = (uint32_t)__cvta_generic_to_shared(sB) + (uint32_t)(brow * PB_PITCH + bn8) * 2;

#define LOADKP(stage, kt) do {                                                  \
        const uint32_t ao_ = (uint32_t)(stage) * (ABUF * 2);                    \
        const uint32_t bo_ = (uint32_t)(stage) * (PBUF * 2);                    \
        const size_t kofs_ = (size_t)(kt) * 32;                                 \
        CP_ASYNC_Z(dA + ao_, gA + kofs_, aok);                                  \
        CP_ASYNC(dB + bo_, gB + kofs_ * CHID);                                  \
        asm volatile("cp.async.commit_group;");                                 \
    } while (0)

    LOADKP(0, 0);
    LOADKP(1, 1);
    LOADKP(2, 2);

    float acc[2][4][4] = {};

    const uint32_t aOff = (uint32_t)((wm * 32 + (lane & 15)) * A_PITCH + ((lane >> 4) << 3)) * 2;
    const uint32_t aB0 = (uint32_t)__cvta_generic_to_shared(sA) + aOff;
    const uint32_t bOff = (uint32_t)(((lane & 7) + ((lane >> 3) & 1) * 8) * PB_PITCH
                                     + wn * 32 + ((lane >> 4) << 3)) * 2;
    const uint32_t bB0 = (uint32_t)__cvta_generic_to_shared(sB) + bOff;

    const int NKT = CCAD / 32;   // 64
    for (int kt = 0; kt < NKT; kt++) {
        const int s = kt & 3;
        if (kt < NKT - 2)       asm volatile("cp.async.wait_group 2;");
        else if (kt == NKT - 2) asm volatile("cp.async.wait_group 1;");
        else                    asm volatile("cp.async.wait_group 0;");
        __syncthreads();

        const uint32_t ah = aB0 + s * (ABUF * 2);
        const uint32_t bh = bB0 + s * (PBUF * 2);
#pragma unroll
        for (int ks = 0; ks < 2; ks++) {
            const uint32_t ka = ah + ks * 32;
            const uint32_t kb = bh + ks * (16 * PB_PITCH * 2);
            uint32_t A0[4], A1[4];
            ldsm4(A0, ka);
            ldsm4(A1, ka + 16 * A_PITCH * 2);
            uint32_t Bf[8];
            ldsm4t(Bf,     kb);
            ldsm4t(Bf + 4, kb + 32);
#pragma unroll
            for (int j = 0; j < 4; j++) {
                mma16816(acc[0][j], A0, &Bf[j * 2]);
                mma16816(acc[1][j], A1, &Bf[j * 2]);
            }
        }
        if (kt + 3 < NKT) {
            LOADKP((kt + 3) & 3, kt + 3);
        }
    }

    const int colb = (lane & 3) << 1;
    const int keyofs = (type >= 2) ? 80 : 0;
#pragma unroll
    for (int fm = 0; fm < 2; fm++) {
        const int r = wm * 32 + fm * 16 + (lane >> 2);
#pragma unroll
        for (int rr = 0; rr < 2; rr++) {
            const int row = r + rr * 8;
            if (row >= M) continue;
            const int key = keyofs + row;
#pragma unroll
            for (int j = 0; j < 4; j++) {
                const int cc = n0 + wn * 32 + j * 8 + colb;
                const int h = cc >> 6, d = cc & 63;
                const float v0 = acc[fm][j][rr * 2 + 0];
                const float v1 = acc[fm][j][rr * 2 + 1];
                if ((type & 1) == 0) {
                    __half* p = g_kth + ((size_t)(b * CNH + h) * 64) * KT_PITCH;
                    p[(size_t)d * KT_PITCH + key]       = __float2half(v0);
                    p[(size_t)(d + 1) * KT_PITCH + key] = __float2half(v1);
                } else {
                    __half* p = g_kvh + ((size_t)(b * CNH + h) * 96 + key) * V_PITCH;
                    *(__half2*)(p + d) = __floats2half2_rn(v0, v1);
                }
            }
        }
    }
#undef LOADKP
}

// =====================================================================
// FUSED Q-GEMM + attention v2: CTA 128x128 = 2 heads, 256 thr / 8 warps
// (wm 4 x wn 2), warp tile 32x64, 3-stage mainloop, 2 CTAs/SM.
// =====================================================================
__global__ __launch_bounds__(256, 2) void qgemm_attn(const int* __restrict__ idx_alter)
{
    extern __shared__ __align__(16) char sm[];
    __half* sA  = (__half*)sm;
    __half* sB  = sA + 3 * ABUF;
    __half* sKt = sB + 3 * PBUF;
    __half* sV  = sKt + KT2_HALVES;

    const int tid = threadIdx.x;
    const int m0 = blockIdx.x * 128, n0 = blockIdx.y * 128;
    const int b = blockIdx.x >> 5;            // 32 m-tiles per batch
    const int hgbase = n0 >> 6;               // first of 2 heads
    const int lane = tid & 31, warp = tid >> 5;
    const int wm = warp & 3, wn = warp >> 2;  // 4 x 2 warps

    // ---- KV staging: ONE cp.async group, committed FIRST ----
    {
        const uint32_t dkt = (uint32_t)__cvta_generic_to_shared(sKt);
        const uint32_t dv  = (uint32_t)__cvta_generic_to_shared(sV);
        const __half* skt = g_kth + (size_t)(b * CNH + hgbase) * 64 * KT_PITCH;
        const __half* sv  = g_kvh + (size_t)(b * CNH + hgbase) * 96 * V_PITCH;
        for (int i = tid; i < KT2_HALVES / 8; i += 256) CP_ASYNC(dkt + i * 16, skt + (size_t)i * 8);
        for (int i = tid; i < V2_HALVES / 8; i += 256)  CP_ASYNC(dv + i * 16, sv + (size_t)i * 8);
        asm volatile("cp.async.commit_group;");
    }

    // ---- GEMM staging setup ----
    const int arow = tid >> 2, ak8 = (tid & 3) << 3;
    const int brow = tid >> 4, bn8 = (tid & 15) << 3;
    const __half* gA = g_hid + (size_t)(m0 + arow) * GK + ak8;
    const __half* gB = g_wq + (size_t)brow * GN + n0 + bn8;
    const uint32_t dA = (uint32_t)__cvta_generic_to_shared(sA) + (uint32_t)(arow * A_PITCH + ak8) * 2;
    const uint32_t dB = (uint32_t)__cvta_generic_to_shared(sB) + (uint32_t)(brow * PB_PITCH + bn8) * 2;

#define LOADK7(stage, kt) do {                                                  \
        const uint32_t ao_ = (uint32_t)(stage) * (ABUF * 2);                    \
        const uint32_t bo_ = (uint32_t)(stage) * (PBUF * 2);                    \
        const size_t ka_ = (size_t)(kt) * 32;                                   \
        CP_ASYNC(dA + ao_, gA + ka_);                                           \
        CP_ASYNC(dA + ao_ + 64 * A_PITCH * 2, gA + (size_t)64 * GK + ka_);      \
        CP_ASYNC(dB + bo_,                     gB + ka_ * GN);                  \
        CP_ASYNC(dB + bo_ + 16 * PB_PITCH * 2, gB + (ka_ + 16) * GN);           \
        asm volatile("cp.async.commit_group;");                                 \
    } while (0)

    LOADK7(0, 0);
    LOADK7(1, 1);

    float acc[2][8][4] = {};

    const uint32_t aOff = (uint32_t)((wm * 32 + (lane & 15)) * A_PITCH + ((lane >> 4) << 3)) * 2;
    const uint32_t aB0 = (uint32_t)__cvta_generic_to_shared(sA) + aOff;
    const uint32_t bOff = (uint32_t)(((lane & 7) + ((lane >> 3) & 1) * 8) * PB_PITCH
                                     + wn * 64 + ((lane >> 4) << 3)) * 2;
    const uint32_t bB0 = (uint32_t)__cvta_generic_to_shared(sB) + bOff;

    const int NKT = GK / 32;   // 40
    for (int kt = 0; kt < NKT; kt++) {
        const int s = kt % 3;
        // FIFO: KV group is oldest, completes before L(k0).
        if (kt < NKT - 1) asm volatile("cp.async.wait_group 1;");
        else              asm volatile("cp.async.wait_group 0;");
        __syncthreads();

        const uint32_t ah = aB0 + s * (ABUF * 2);
        const uint32_t bh = bB0 + s * (PBUF * 2);
#pragma unroll
        for (int ks = 0; ks < 2; ks++) {
            const uint32_t ka = ah + ks * 32;
            const uint32_t kb = bh + ks * (16 * PB_PITCH * 2);
            uint32_t A0[4], A1[4];
            ldsm4(A0, ka);
            ldsm4(A1, ka + 16 * A_PITCH * 2);
            uint32_t Bf[16];
#pragma unroll
            for (int t = 0; t < 4; t++) ldsm4t(Bf + t * 4, kb + t * 32);
#pragma unroll
            for (int j = 0; j < 8; j++) {
                mma16816(acc[0][j], A0, &Bf[j * 2]);
                mma16816(acc[1][j], A1, &Bf[j * 2]);
            }
        }
        if (kt + 2 < NKT) {
            LOADK7((kt + 2) % 3, kt + 2);
        }
    }
    __syncthreads();

    // ---- convert Q accumulators to fp16 A-fragments (scale 1/8 folded) ----
    uint32_t qa[2][16];
#pragma unroll
    for (int f = 0; f < 2; f++)
#pragma unroll
        for (int kc = 0; kc < 4; kc++) {
            const __half2 a0 = __floats2half2_rn(acc[f][2 * kc][0] * 0.125f, acc[f][2 * kc][1] * 0.125f);
            const __half2 a1 = __floats2half2_rn(acc[f][2 * kc][2] * 0.125f, acc[f][2 * kc][3] * 0.125f);
            const __half2 a2 = __floats2half2_rn(acc[f][2 * kc + 1][0] * 0.125f, acc[f][2 * kc + 1][1] * 0.125f);
            const __half2 a3 = __floats2half2_rn(acc[f][2 * kc + 1][2] * 0.125f, acc[f][2 * kc + 1][3] * 0.125f);
            qa[f][kc * 4 + 0] = *(const uint32_t*)&a0;
            qa[f][kc * 4 + 1] = *(const uint32_t*)&a1;
            qa[f][kc * 4 + 2] = *(const uint32_t*)&a2;
            qa[f][kc * 4 + 3] = *(const uint32_t*)&a3;
        }

    const int sidx = idx_alter[b];
    const int h = wn;   // head within the 2-head tile
    const uint32_t ktb = (uint32_t)__cvta_generic_to_shared(sKt) + (uint32_t)h * 64 * KT_PITCH * 2
        + (uint32_t)(((lane & 7) + ((lane >> 3) & 1) * 8) * KT_PITCH + ((lane >> 4) << 3)) * 2;
    const uint32_t vb = (uint32_t)__cvta_generic_to_shared(sV) + (uint32_t)h * 96 * V_PITCH * 2
        + (uint32_t)(((lane & 7) + ((lane >> 3) & 1) * 8) * V_PITCH + ((lane >> 4) << 3)) * 2;
    const int colb = (lane & 3) << 1;
    const int r = lane >> 2;

#pragma unroll
    for (int f = 0; f < 2; f++) {
        float c[11][4] = {};
#pragma unroll
        for (int kc = 0; kc < 4; kc++) {
            uint32_t Bf[24];
#pragma unroll
            for (int t = 0; t < 6; t++)
                ldsm4t(&Bf[t * 4], ktb + kc * (16 * KT_PITCH * 2) + t * 32);
#pragma unroll
            for (int ff = 0; ff < 11; ff++) mma16816(c[ff], &qa[f][kc * 4], &Bf[ff * 2]);
        }

        // txt softmax (cols 0-76)
        float m0v = -1e30f, m1v = -1e30f;
#pragma unroll
        for (int ff = 0; ff < 10; ff++) {
            const int col = ff * 8 + colb;
            if (col < CLTXT)     { m0v = fmaxf(m0v, c[ff][0]); m1v = fmaxf(m1v, c[ff][2]); }
            if (col + 1 < CLTXT) { m0v = fmaxf(m0v, c[ff][1]); m1v = fmaxf(m1v, c[ff][3]); }
        }
        m0v = fmaxf(m0v, __shfl_xor_sync(0xffffffffu, m0v, 1));
        m0v = fmaxf(m0v, __shfl_xor_sync(0xffffffffu, m0v, 2));
        m1v = fmaxf(m1v, __shfl_xor_sync(0xffffffffu, m1v, 1));
        m1v = fmaxf(m1v, __shfl_xor_sync(0xffffffffu, m1v, 2));
        float s0 = 0.f, s1 = 0.f;
#pragma unroll
        for (int ff = 0; ff < 10; ff++) {
            const int col = ff * 8 + colb;
            c[ff][0] = (col < CLTXT)     ? __expf(c[ff][0] - m0v) : 0.f;
            c[ff][1] = (col + 1 < CLTXT) ? __expf(c[ff][1] - m0v) : 0.f;
            c[ff][2] = (col < CLTXT)     ? __expf(c[ff][2] - m1v) : 0.f;
            c[ff][3] = (col + 1 < CLTXT) ? __expf(c[ff][3] - m1v) : 0.f;
            s0 += c[ff][0] + c[ff][1];
            s1 += c[ff][2] + c[ff][3];
        }
        s0 += __shfl_xor_sync(0xffffffffu, s0, 1);
        s0 += __shfl_xor_sync(0xffffffffu, s0, 2);
        s1 += __shfl_xor_sync(0xffffffffu, s1, 1);
        s1 += __shfl_xor_sync(0xffffffffu, s1, 2);
        const float inv0 = 1.f / s0, inv1 = 1.f / s1;
#pragma unroll
        for (int ff = 0; ff < 10; ff++) {
            c[ff][0] *= inv0; c[ff][1] *= inv0;
            c[ff][2] *= inv1; c[ff][3] *= inv1;
        }

        // w_s extraction + zero col sidx
        const int fs = sidx >> 3, se = sidx & 1, hold = (sidx & 7) >> 1;
        float cand0 = 0.f, cand1 = 0.f;
#pragma unroll
        for (int ff = 0; ff < 10; ff++) {
            if (ff == fs) {
                cand0 = se ? c[ff][1] : c[ff][0];
                cand1 = se ? c[ff][3] : c[ff][2];
            }
        }
        const int src = (lane & ~3) | hold;
        const float ws0 = __shfl_sync(0xffffffffu, cand0, src);
        const float ws1 = __shfl_sync(0xffffffffu, cand1, src);
        if ((lane & 3) == hold) {
#pragma unroll
            for (int ff = 0; ff < 10; ff++) {
                if (ff == fs) { c[ff][se] = 0.f; c[ff][2 + se] = 0.f; }
            }
        }

        // nested softmax (frag 10, cols 80-83) scaled by w_s
        {
            const bool nv = (lane & 3) < 2;
            const float n00 = nv ? c[10][0] : -1e30f;
            const float n01 = nv ? c[10][1] : -1e30f;
            const float n10 = nv ? c[10][2] : -1e30f;
            const float n11 = nv ? c[10][3] : -1e30f;
            float nm0 = fmaxf(n00, n01), nm1 = fmaxf(n10, n11);
            nm0 = fmaxf(nm0, __shfl_xor_sync(0xffffffffu, nm0, 1));
            nm0 = fmaxf(nm0, __shfl_xor_sync(0xffffffffu, nm0, 2));
            nm1 = fmaxf(nm1, __shfl_xor_sync(0xffffffffu, nm1, 1));
            nm1 = fmaxf(nm1, __shfl_xor_sync(0xffffffffu, nm1, 2));
            const float e00 = nv ? __expf(n00 - nm0) : 0.f;
            const float e01 = nv ? __expf(n01 - nm0) : 0.f;
            const float e10 = nv ? __expf(n10 - nm1) : 0.f;
            const float e11 = nv ? __expf(n11 - nm1) : 0.f;
            float ns0 = e00 + e01, ns1 = e10 + e11;
            ns0 += __shfl_xor_sync(0xffffffffu, ns0, 1);
            ns0 += __shfl_xor_sync(0xffffffffu, ns0, 2);
            ns1 += __shfl_xor_sync(0xffffffffu, ns1, 1);
            ns1 += __shfl_xor_sync(0xffffffffu, ns1, 2);
            const float sc0 = ws0 / ns0, sc1 = ws1 / ns1;
            c[10][0] = e00 * sc0; c[10][1] = e01 * sc0;
            c[10][2] = e10 * sc1; c[10][3] = e11 * sc1;
        }

        // weights -> A fragments
        uint32_t aw[12][2];
#pragma unroll
        for (int ff = 0; ff < 11; ff++) {
            const __half2 lo = __floats2half2_rn(c[ff][0], c[ff][1]);
            const __half2 hi = __floats2half2_rn(c[ff][2], c[ff][3]);
            aw[ff][0] = *(const uint32_t*)&lo;
            aw[ff][1] = *(const uint32_t*)&hi;
        }
        aw[11][0] = 0; aw[11][1] = 0;

        // mma2: out = W' @ V'
        float o[8][4] = {};
#pragma unroll
        for (int g = 0; g < 6; g++) {
            const uint32_t A2[4] = { aw[2 * g][0], aw[2 * g][1], aw[2 * g + 1][0], aw[2 * g + 1][1] };
            uint32_t Bf[16];
#pragma unroll
            for (int t = 0; t < 4; t++)
                ldsm4t(&Bf[t * 4], vb + g * (16 * V_PITCH * 2) + t * 32);
#pragma unroll
            for (int ff = 0; ff < 8; ff++) mma16816(o[ff], A2, &Bf[ff * 2]);
        }

        // store fp16 to g_attn
        const size_t tok0 = (size_t)(m0 + wm * 32 + f * 16 + r);
        const size_t base0 = tok0 * CHID + n0 + wn * 64;
        const size_t base1 = base0 + (size_t)8 * CHID;
#pragma unroll
        for (int ff = 0; ff < 8; ff++) {
            const int dd = ff * 8 + colb;
            *(__half2*)(g_attn + base0 + dd) = __floats2half2_rn(o[ff][0], o[ff][1]);
            *(__half2*)(g_attn + base1 + dd) = __floats2half2_rn(o[ff][2], o[ff][3]);
        }
    }
#undef LOADK7
}

// ---------------- launch ----------------
extern "C" void kernel_launch(void* const* d_in, const int* in_sizes, int n_in,
                              void* d_out, int out_size)
{
    (void)in_sizes; (void)n_in; (void)out_size;
    const float* hidden = (const float*)d_in[0];
    const float* enc    = (const float*)d_in[1];
    const int*   idx    = (const int*)  d_in[2];
    const float* Wq     = (const float*)d_in[3];
    const float* Wk     = (const float*)d_in[4];
    const float* Wv     = (const float*)d_in[5];
    const float* Wkn    = (const float*)d_in[6];
    const float* Wvn    = (const float*)d_in[7];
    const float* Wout   = (const float*)d_in[8];
    const float* bout   = (const float*)d_in[9];
    float* out = (float*)d_out;

    __half *hidp, *wqp, *wop, *atp, *encp, *wkp, *wvp, *wknp, *wvnp;
    cudaGetSymbolAddress((void**)&hidp, g_hid);
    cudaGetSymbolAddress((void**)&wqp,  g_wq);
    cudaGetSymbolAddress((void**)&wop,  g_wo);
    cudaGetSymbolAddress((void**)&atp,  g_attn);
    cudaGetSymbolAddress((void**)&encp, g_enc);
    cudaGetSymbolAddress((void**)&wkp,  g_wk);
    cudaGetSymbolAddress((void**)&wvp,  g_wv);
    cudaGetSymbolAddress((void**)&wknp, g_wkn);
    cudaGetSymbolAddress((void**)&wvnp, g_wvn);

    cudaFuncSetAttribute(gemm_f16, cudaFuncAttributeMaxDynamicSharedMemorySize, GEMM_SMEM);
    cudaFuncSetAttribute(proj_f16, cudaFuncAttributeMaxDynamicSharedMemorySize, PROJ_SMEM);
    cudaFuncSetAttribute(qgemm_attn, cudaFuncAttributeMaxDynamicSharedMemorySize, FUSE_SMEM);

    // 1) ALL conversions, one launch (8 segments)
    CvtArgs ca;
    ca.s[0] = { hidden, hidp, GM * GK };
    ca.s[1] = { Wq,   wqp,  GK * GN };
    ca.s[2] = { Wout, wop,  GK * GN };
    ca.s[3] = { Wk,   wkp,  CCAD * CHID };
    ca.s[4] = { Wv,   wvp,  CCAD * CHID };
    ca.s[5] = { Wkn,  wknp, CCAD * CHID };
    ca.s[6] = { Wvn,  wvnp, CCAD * CHID };
    ca.s[7] = { enc,  encp, CB * CENCL * CCAD };
    cvt_multi<<<dim3(160, 8), 512>>>(ca);

    // 2) K/V/KN/VN projections -> attention-ready fp16 layouts
    proj_f16<<<dim3(CB, CHID / 128, 4), 512, PROJ_SMEM>>>();

    // 3) FUSED: Q-GEMM + attention -> g_attn fp16 (640 CTAs, 2/SM)
    qgemm_attn<<<dim3(GM / 128, GN / 128), 256, FUSE_SMEM>>>(idx);

    // 4) out = attn @ Wout + bias (640 CTAs, 2/SM)
    gemm_f16<<<dim3(GM / 128, GN / 128), 256, GEMM_SMEM>>>(atp, wop, bout, out);
}